// round 10
// baseline (speedup 1.0000x reference)
#include <cuda_runtime.h>
#include <cuda_bf16.h>
#include <math.h>
#include <stdint.h>

#define DMODEL 2048
#define TDMODEL 6144
#define NR 4096      // B*S rows
#define NH 16
#define HD 128
#define SEQ 2048
#define NB 2

// ---------------------------------------------------------------------------
// Scratch (no allocations allowed)
// ---------------------------------------------------------------------------
__device__ __nv_bfloat16 g_xh[(size_t)NR * DMODEL];
__device__ __nv_bfloat16 g_xl[(size_t)NR * DMODEL];
__device__ __nv_bfloat16 g_wqkvh[(size_t)TDMODEL * DMODEL];
__device__ __nv_bfloat16 g_wqkvl[(size_t)TDMODEL * DMODEL];
__device__ __nv_bfloat16 g_woh[(size_t)DMODEL * DMODEL];
__device__ __nv_bfloat16 g_wol[(size_t)DMODEL * DMODEL];
__device__ __nv_bfloat16 g_qkvh[(size_t)NR * TDMODEL];     // Q,K columns used
__device__ __nv_bfloat16 g_vth[(size_t)NB * NH * HD * SEQ]; // [b][h][d][tok]
__device__ __nv_bfloat16 g_vtl[(size_t)NB * NH * HD * SEQ];
__device__ __nv_bfloat16 g_ath[(size_t)NR * DMODEL];
__device__ __nv_bfloat16 g_atl[(size_t)NR * DMODEL];

// ---------------------------------------------------------------------------
// PTX helpers (sm_80+ portable)
// ---------------------------------------------------------------------------
__device__ __forceinline__ uint32_t smem_u32(const void* p) {
    uint32_t a;
    asm("{ .reg .u64 t; cvta.to.shared.u64 t, %1; cvt.u32.u64 %0, t; }" : "=r"(a) : "l"(p));
    return a;
}
__device__ __forceinline__ void cp16(uint32_t dst, const void* src) {
    asm volatile("cp.async.cg.shared.global [%0], [%1], 16;" :: "r"(dst), "l"(src));
}
__device__ __forceinline__ void ldsm_x4(uint32_t addr, uint32_t& r0, uint32_t& r1,
                                        uint32_t& r2, uint32_t& r3) {
    asm volatile("ldmatrix.sync.aligned.m8n8.x4.shared.b16 {%0,%1,%2,%3}, [%4];"
                 : "=r"(r0), "=r"(r1), "=r"(r2), "=r"(r3) : "r"(addr));
}
__device__ __forceinline__ void mma_bf16(float* d, const uint32_t* a,
                                         uint32_t b0, uint32_t b1) {
    asm volatile(
        "mma.sync.aligned.m16n8k16.row.col.f32.bf16.bf16.f32 "
        "{%0,%1,%2,%3}, {%4,%5,%6,%7}, {%8,%9}, {%0,%1,%2,%3};"
        : "+f"(d[0]), "+f"(d[1]), "+f"(d[2]), "+f"(d[3])
        : "r"(a[0]), "r"(a[1]), "r"(a[2]), "r"(a[3]), "r"(b0), "r"(b1));
}
__device__ __forceinline__ float ex2f(float x) {
    float y; asm("ex2.approx.f32 %0, %1;" : "=f"(y) : "f"(x)); return y;
}
// pack {lo, hi} fp32 -> bf16x2 (lo in bits [0:16))
__device__ __forceinline__ uint32_t pack2bf(float lo, float hi) {
    uint32_t r;
    asm("cvt.rn.bf16x2.f32 %0, %1, %2;" : "=r"(r) : "f"(hi), "f"(lo));
    return r;
}
__device__ __forceinline__ float bf_hi_f(float v) {
    return __bfloat162float(__float2bfloat16(v));
}
// swizzle for 64 B/row smem tiles: flips chunk bits [4:6) by row bits [7:9)
__device__ __forceinline__ uint32_t swz64(uint32_t o) {
    return o ^ (((o >> 7) & 3u) << 4);
}

// ---------------------------------------------------------------------------
// Split fp32 -> bf16 hi + bf16 lo (residual)
// ---------------------------------------------------------------------------
__global__ void split_kernel(const float* __restrict__ s,
                             __nv_bfloat16* __restrict__ h,
                             __nv_bfloat16* __restrict__ l, int n4)
{
    int i = blockIdx.x * blockDim.x + threadIdx.x;
    if (i >= n4) return;
    float4 v = ((const float4*)s)[i];
    uint2 uh, ul;
    uh.x = pack2bf(v.x, v.y);
    uh.y = pack2bf(v.z, v.w);
    ul.x = pack2bf(v.x - bf_hi_f(v.x), v.y - bf_hi_f(v.y));
    ul.y = pack2bf(v.z - bf_hi_f(v.z), v.w - bf_hi_f(v.w));
    ((uint2*)h)[i] = uh;
    ((uint2*)l)[i] = ul;
}

// ---------------------------------------------------------------------------
// Fused QKV projection GEMM (R8 geometry: 128x128 CTA, 64x32 warp, NSTG=3).
// blockIdx.x < 32  -> Q,K columns: single-pass bf16, write qkvh only.
// blockIdx.x >= 32 -> V columns: 3-pass split, write transposed vt hi/lo.
// ---------------------------------------------------------------------------
#define TS 8192u                         // 128 rows x 64 B per operand stage
#define NSTG 3
#define ALOFF (2u * NSTG * TS)           // hi -> lo operand base distance

__global__ __launch_bounds__(256, 2)
void gemm_qkv(const __nv_bfloat16* __restrict__ Ah, const __nv_bfloat16* __restrict__ Al,
              const __nv_bfloat16* __restrict__ Bh, const __nv_bfloat16* __restrict__ Bl,
              __nv_bfloat16* __restrict__ qvh,
              __nv_bfloat16* __restrict__ vth, __nv_bfloat16* __restrict__ vtl)
{
    const int K = DMODEL;
    extern __shared__ char smem[];
    const uint32_t sb = (smem_u32(smem) + 1023u) & ~1023u;
    const uint32_t sAh = sb;
    const uint32_t sBh = sb + NSTG * TS;

    const int tid = threadIdx.x, lane = tid & 31, wid = tid >> 5;
    const int bm = blockIdx.y * 128, bn = blockIdx.x * 128;
    const bool v3 = (blockIdx.x >= 32);          // V region -> 3-pass
    const int m0 = (wid & 1) * 64, n0 = (wid >> 1) * 32;

    const char* gAh = (const char*)(Ah + (size_t)bm * K);
    const char* gAl = (const char*)(Al + (size_t)bm * K);
    const char* gBh = (const char*)(Bh + (size_t)bn * K);
    const char* gBl = (const char*)(Bl + (size_t)bn * K);

    float acc[4][4][4];
#pragma unroll
    for (int i = 0; i < 4; i++)
#pragma unroll
        for (int j = 0; j < 4; j++)
#pragma unroll
            for (int c = 0; c < 4; c++) acc[i][j][c] = 0.f;

    // ---- precomputed cp.async smem offsets ----
    const int lrow = tid >> 2;
    const int lch = (tid & 3) * 16;
    uint32_t cpRel[2], goRow[2];
#pragma unroll
    for (int t = 0; t < 2; t++) {
        cpRel[t] = swz64((uint32_t)((lrow + t * 64) * 64) + lch);
        goRow[t] = (uint32_t)((lrow + t * 64) * K * 2) + lch;
    }

    // ---- precomputed ldsm addresses (stage 0) ----
    const int lr = lane & 15;
    const uint32_t lcb = (uint32_t)((lane >> 4) * 16);
    uint32_t aAddr[4][2], bAddr[2][2];
#pragma unroll
    for (int mt = 0; mt < 4; mt++) {
        uint32_t row = (uint32_t)(m0 + mt * 16 + lr);
        uint32_t swz = ((row >> 1) & 3u) << 4;
#pragma unroll
        for (int ks = 0; ks < 2; ks++)
            aAddr[mt][ks] = sAh + row * 64 + (((uint32_t)(ks * 32) | lcb) ^ swz);
    }
#pragma unroll
    for (int g = 0; g < 2; g++) {
        uint32_t row = (uint32_t)(n0 + g * 16 + lr);
        uint32_t swz = ((row >> 1) & 3u) << 4;
#pragma unroll
        for (int ks = 0; ks < 2; ks++)
            bAddr[g][ks] = sBh + row * 64 + (((uint32_t)(ks * 32) | lcb) ^ swz);
    }

    auto load_stage = [&](int kb, uint32_t bufo) {
        const uint32_t gofs = (uint32_t)kb * 64;
#pragma unroll
        for (int t = 0; t < 2; t++) {
            uint32_t so = cpRel[t] + bufo;
            uint32_t go = goRow[t] + gofs;
            cp16(sAh + so, gAh + go);
            cp16(sBh + so, gBh + go);
            if (v3) {
                cp16(sAh + ALOFF + so, gAl + go);
                cp16(sBh + ALOFF + so, gBl + go);
            }
        }
        asm volatile("cp.async.commit_group;" ::: "memory");
    };

    const int nk = K / 32;
    load_stage(0, 0);
    load_stage(1, TS);

    for (int kb0 = 0; kb0 < nk; kb0 += NSTG) {
#pragma unroll
        for (int u = 0; u < NSTG; u++) {
            const int kb = kb0 + u;
            if (kb >= nk) break;
            asm volatile("cp.async.wait_group %0;" :: "n"(NSTG - 2) : "memory");
            __syncthreads();
            {
                int nkb = kb + NSTG - 1;
                const uint32_t nbufo = (uint32_t)((u + NSTG - 1) % NSTG) * TS;
                if (nkb < nk) load_stage(nkb, nbufo);
                else asm volatile("cp.async.commit_group;" ::: "memory");
            }
            const uint32_t bufo = (uint32_t)u * TS;

#pragma unroll
            for (int ks = 0; ks < 2; ks++) {
                uint32_t ah[4][4], al[4][4], bh[2][4], bl[2][4];
#pragma unroll
                for (int mt = 0; mt < 4; mt++) {
                    uint32_t addr = aAddr[mt][ks] + bufo;
                    ldsm_x4(addr, ah[mt][0], ah[mt][1], ah[mt][2], ah[mt][3]);
                    if (v3)
                        ldsm_x4(addr + ALOFF, al[mt][0], al[mt][1], al[mt][2], al[mt][3]);
                }
#pragma unroll
                for (int g = 0; g < 2; g++) {
                    uint32_t addr = bAddr[g][ks] + bufo;
                    ldsm_x4(addr, bh[g][0], bh[g][1], bh[g][2], bh[g][3]);
                    if (v3)
                        ldsm_x4(addr + ALOFF, bl[g][0], bl[g][1], bl[g][2], bl[g][3]);
                }
#pragma unroll
                for (int mt = 0; mt < 4; mt++)
#pragma unroll
                    for (int nt = 0; nt < 4; nt++) {
                        const int g = nt >> 1, p = nt & 1;
                        mma_bf16(acc[mt][nt], ah[mt], bh[g][p], bh[g][p + 2]);
                        if (v3) {
                            mma_bf16(acc[mt][nt], ah[mt], bl[g][p], bl[g][p + 2]);
                            mma_bf16(acc[mt][nt], al[mt], bh[g][p], bh[g][p + 2]);
                        }
                    }
            }
        }
    }

    const int gr = lane >> 2, gc = (lane & 3) * 2;
    if (!v3) {
        // ---- Q,K epilogue: bf16 hi only, row-major qkv layout ----
#pragma unroll
        for (int mt = 0; mt < 4; mt++)
#pragma unroll
            for (int nt = 0; nt < 4; nt++) {
                int r = bm + m0 + mt * 16 + gr;
                int cix = bn + n0 + nt * 8 + gc;
#pragma unroll
                for (int half = 0; half < 2; half++) {
                    float v0 = acc[mt][nt][half * 2], v1 = acc[mt][nt][half * 2 + 1];
                    *(uint32_t*)&qvh[(size_t)(r + half * 8) * TDMODEL + cix] =
                        pack2bf(v0, v1);
                }
            }
    } else {
        // ---- V epilogue: split hi/lo, transposed vt[(b,h)][d][tok] ----
        const int nbase = bn - 4096 + n0;
#pragma unroll
        for (int mt = 0; mt < 4; mt++)
#pragma unroll
            for (int nt = 0; nt < 4; nt++) {
#pragma unroll
                for (int half = 0; half < 2; half++) {
                    int r = bm + m0 + mt * 16 + gr + half * 8;
                    int bb = r >> 11, tok = r & 2047;
#pragma unroll
                    for (int cc = 0; cc < 2; cc++) {
                        int n = nbase + nt * 8 + gc + cc;
                        size_t o = ((size_t)(bb * NH * HD + n)) * SEQ + tok;
                        float v = acc[mt][nt][half * 2 + cc];
                        vth[o] = __float2bfloat16(v);
                        vtl[o] = __float2bfloat16(v - bf_hi_f(v));
                    }
                }
            }
    }
}

// ---------------------------------------------------------------------------
// Output GEMM (R8 geometry, 3-pass, fp32 epilogue).
// ---------------------------------------------------------------------------
__global__ __launch_bounds__(256, 2)
void gemm_out(const __nv_bfloat16* __restrict__ Ah, const __nv_bfloat16* __restrict__ Al,
              const __nv_bfloat16* __restrict__ Bh, const __nv_bfloat16* __restrict__ Bl,
              float* __restrict__ C)
{
    const int K = DMODEL, ldc = DMODEL;
    extern __shared__ char smem[];
    const uint32_t sb = (smem_u32(smem) + 1023u) & ~1023u;
    const uint32_t sAh = sb;
    const uint32_t sBh = sb + NSTG * TS;

    const int tid = threadIdx.x, lane = tid & 31, wid = tid >> 5;
    const int bm = blockIdx.y * 128, bn = blockIdx.x * 128;
    const int m0 = (wid & 1) * 64, n0 = (wid >> 1) * 32;

    const char* gAh = (const char*)(Ah + (size_t)bm * K);
    const char* gAl = (const char*)(Al + (size_t)bm * K);
    const char* gBh = (const char*)(Bh + (size_t)bn * K);
    const char* gBl = (const char*)(Bl + (size_t)bn * K);

    float acc[4][4][4];
#pragma unroll
    for (int i = 0; i < 4; i++)
#pragma unroll
        for (int j = 0; j < 4; j++)
#pragma unroll
            for (int c = 0; c < 4; c++) acc[i][j][c] = 0.f;

    const int lrow = tid >> 2;
    const int lch = (tid & 3) * 16;
    uint32_t cpRel[2], goRow[2];
#pragma unroll
    for (int t = 0; t < 2; t++) {
        cpRel[t] = swz64((uint32_t)((lrow + t * 64) * 64) + lch);
        goRow[t] = (uint32_t)((lrow + t * 64) * K * 2) + lch;
    }

    const int lr = lane & 15;
    const uint32_t lcb = (uint32_t)((lane >> 4) * 16);
    uint32_t aAddr[4][2], bAddr[2][2];
#pragma unroll
    for (int mt = 0; mt < 4; mt++) {
        uint32_t row = (uint32_t)(m0 + mt * 16 + lr);
        uint32_t swz = ((row >> 1) & 3u) << 4;
#pragma unroll
        for (int ks = 0; ks < 2; ks++)
            aAddr[mt][ks] = sAh + row * 64 + (((uint32_t)(ks * 32) | lcb) ^ swz);
    }
#pragma unroll
    for (int g = 0; g < 2; g++) {
        uint32_t row = (uint32_t)(n0 + g * 16 + lr);
        uint32_t swz = ((row >> 1) & 3u) << 4;
#pragma unroll
        for (int ks = 0; ks < 2; ks++)
            bAddr[g][ks] = sBh + row * 64 + (((uint32_t)(ks * 32) | lcb) ^ swz);
    }

    auto load_stage = [&](int kb, uint32_t bufo) {
        const uint32_t gofs = (uint32_t)kb * 64;
#pragma unroll
        for (int t = 0; t < 2; t++) {
            uint32_t so = cpRel[t] + bufo;
            uint32_t go = goRow[t] + gofs;
            cp16(sAh + so, gAh + go);
            cp16(sBh + so, gBh + go);
            cp16(sAh + ALOFF + so, gAl + go);
            cp16(sBh + ALOFF + so, gBl + go);
        }
        asm volatile("cp.async.commit_group;" ::: "memory");
    };

    const int nk = K / 32;
    load_stage(0, 0);
    load_stage(1, TS);

    for (int kb0 = 0; kb0 < nk; kb0 += NSTG) {
#pragma unroll
        for (int u = 0; u < NSTG; u++) {
            const int kb = kb0 + u;
            if (kb >= nk) break;
            asm volatile("cp.async.wait_group %0;" :: "n"(NSTG - 2) : "memory");
            __syncthreads();
            {
                int nkb = kb + NSTG - 1;
                const uint32_t nbufo = (uint32_t)((u + NSTG - 1) % NSTG) * TS;
                if (nkb < nk) load_stage(nkb, nbufo);
                else asm volatile("cp.async.commit_group;" ::: "memory");
            }
            const uint32_t bufo = (uint32_t)u * TS;

#pragma unroll
            for (int ks = 0; ks < 2; ks++) {
                uint32_t ah[4][4], al[4][4], bh[2][4], bl[2][4];
#pragma unroll
                for (int mt = 0; mt < 4; mt++) {
                    uint32_t addr = aAddr[mt][ks] + bufo;
                    ldsm_x4(addr, ah[mt][0], ah[mt][1], ah[mt][2], ah[mt][3]);
                    ldsm_x4(addr + ALOFF, al[mt][0], al[mt][1], al[mt][2], al[mt][3]);
                }
#pragma unroll
                for (int g = 0; g < 2; g++) {
                    uint32_t addr = bAddr[g][ks] + bufo;
                    ldsm_x4(addr, bh[g][0], bh[g][1], bh[g][2], bh[g][3]);
                    ldsm_x4(addr + ALOFF, bl[g][0], bl[g][1], bl[g][2], bl[g][3]);
                }
#pragma unroll
                for (int mt = 0; mt < 4; mt++)
#pragma unroll
                    for (int nt = 0; nt < 4; nt++) {
                        const int g = nt >> 1, p = nt & 1;
                        mma_bf16(acc[mt][nt], ah[mt], bh[g][p], bh[g][p + 2]);
                        mma_bf16(acc[mt][nt], ah[mt], bl[g][p], bl[g][p + 2]);
                        mma_bf16(acc[mt][nt], al[mt], bh[g][p], bh[g][p + 2]);
                    }
            }
        }
    }

    const int gr = lane >> 2, gc = (lane & 3) * 2;
#pragma unroll
    for (int mt = 0; mt < 4; mt++)
#pragma unroll
        for (int nt = 0; nt < 4; nt++) {
            int r = bm + m0 + mt * 16 + gr;
            int cix = bn + n0 + nt * 8 + gc;
            *(float2*)&C[(size_t)r * ldc + cix] =
                make_float2(acc[mt][nt][0], acc[mt][nt][1]);
            *(float2*)&C[(size_t)(r + 8) * ldc + cix] =
                make_float2(acc[mt][nt][2], acc[mt][nt][3]);
        }
}

#define GEMM3_SMEM (4 * NSTG * TS + 1024)      // 99328

// ---------------------------------------------------------------------------
// Tensor-core causal flash attention (unchanged).
// ---------------------------------------------------------------------------
#define QSTR 136
#define VTSTR 72
#define SM_Q 0
#define SM_K 34816
#define SM_VT 69632
#define ATTN_SMEM_BYTES 143360
#define CEXP 0.12751744f                 // log2(e)/sqrt(128)
#define MASKV (-1e30f)

__global__ __launch_bounds__(256, 1)
void attn_mma(const __nv_bfloat16* __restrict__ qkvh,
              const __nv_bfloat16* __restrict__ vth,
              const __nv_bfloat16* __restrict__ vtl,
              __nv_bfloat16* __restrict__ ath, __nv_bfloat16* __restrict__ atl)
{
    extern __shared__ char smem[];
    const uint32_t sb = smem_u32(smem);

    const int tid = threadIdx.x, lane = tid & 31, wid = tid >> 5;
    const int qb = 15 - blockIdx.x;
    const int h = blockIdx.y, b = blockIdx.z;
    const int wq0 = wid * 16;
    const int lr = lane & 15, lc = (lane >> 4) * 8;
    const int gr = lane >> 2, gc = (lane & 3) * 2;

    const char* gQ = (const char*)qkvh + ((size_t)(b * SEQ + qb * 128)) * (TDMODEL * 2)
                     + h * 256;
    const char* gK = (const char*)qkvh + ((size_t)(b * SEQ)) * (TDMODEL * 2)
                     + DMODEL * 2 + h * 256;
    const char* gVh = (const char*)vth + ((size_t)((b * NH + h) * HD)) * (SEQ * 2);
    const char* gVl = (const char*)vtl + ((size_t)((b * NH + h) * HD)) * (SEQ * 2);

    {
#pragma unroll
        for (int i = 0; i < 8; i++) {
            int c = tid + i * 256;
            int row = c >> 4, coff = (c & 15) * 16;
            cp16(sb + SM_Q + row * (QSTR * 2) + coff, gQ + (size_t)row * 12288 + coff);
        }
        asm volatile("cp.async.commit_group;" ::: "memory");
    }
    auto load_stage = [&](int kt, int buf) {
        const uint32_t kb_ = sb + SM_K + buf * 17408;
        const uint32_t vb_ = sb + SM_VT + buf * 36864;
#pragma unroll
        for (int i = 0; i < 4; i++) {
            int c = tid + i * 256;
            int row = c >> 4, coff = (c & 15) * 16;
            cp16(kb_ + row * (QSTR * 2) + coff,
                 gK + (size_t)(kt * 64 + row) * 12288 + coff);
        }
#pragma unroll
        for (int i = 0; i < 4; i++) {
            int c = tid + i * 256;
            int row = c >> 3, coff = (c & 7) * 16;
            size_t go = (size_t)row * (SEQ * 2) + (size_t)kt * 128 + coff;
            cp16(vb_ + row * (VTSTR * 2) + coff, gVh + go);
            cp16(vb_ + 18432 + row * (VTSTR * 2) + coff, gVl + go);
        }
        asm volatile("cp.async.commit_group;" ::: "memory");
    };
    load_stage(0, 0);

    uint32_t qf[8][4];
    float acc_o[8][2][4];
#pragma unroll
    for (int gd = 0; gd < 8; gd++)
#pragma unroll
        for (int p = 0; p < 2; p++)
#pragma unroll
            for (int c = 0; c < 4; c++) acc_o[gd][p][c] = 0.f;
    float m0 = MASKV, m1 = MASKV, l0 = 0.f, l1 = 0.f;

    const int ktmax = 2 * qb + 1;
    const int q_row0 = qb * 128 + wq0 + gr;

    for (int kt = 0; kt <= ktmax; kt++) {
        const int buf = kt & 1;
        if (kt < ktmax) {
            load_stage(kt + 1, buf ^ 1);
            asm volatile("cp.async.wait_group 1;" ::: "memory");
        } else {
            asm volatile("cp.async.wait_group 0;" ::: "memory");
        }
        __syncthreads();

        if (kt == 0) {
#pragma unroll
            for (int dc = 0; dc < 8; dc++) {
                uint32_t off = sb + SM_Q + (uint32_t)((wq0 + lr) * QSTR + dc * 16 + lc) * 2;
                ldsm_x4(off, qf[dc][0], qf[dc][1], qf[dc][2], qf[dc][3]);
            }
        }

        const uint32_t kb_ = sb + SM_K + buf * 17408;
        const uint32_t vb_ = sb + SM_VT + buf * 36864;

        float s[4][2][4];
#pragma unroll
        for (int g = 0; g < 4; g++)
#pragma unroll
            for (int p = 0; p < 2; p++)
#pragma unroll
                for (int c = 0; c < 4; c++) s[g][p][c] = 0.f;
#pragma unroll
        for (int dc = 0; dc < 8; dc++)
#pragma unroll
            for (int g = 0; g < 4; g++) {
                uint32_t kbt[4];
                ldsm_x4(kb_ + (uint32_t)((g * 16 + lr) * QSTR + dc * 16 + lc) * 2,
                        kbt[0], kbt[1], kbt[2], kbt[3]);
                mma_bf16(s[g][0], qf[dc], kbt[0], kbt[2]);
                mma_bf16(s[g][1], qf[dc], kbt[1], kbt[3]);
            }

        if (kt >= 2 * qb) {
#pragma unroll
            for (int g = 0; g < 4; g++)
#pragma unroll
                for (int p = 0; p < 2; p++) {
                    int key = kt * 64 + g * 16 + p * 8 + gc;
                    if (key > q_row0)     s[g][p][0] = MASKV;
                    if (key + 1 > q_row0) s[g][p][1] = MASKV;
                    if (key > q_row0 + 8)     s[g][p][2] = MASKV;
                    if (key + 1 > q_row0 + 8) s[g][p][3] = MASKV;
                }
        }

        float t0 = MASKV, t1 = MASKV;
#pragma unroll
        for (int g = 0; g < 4; g++)
#pragma unroll
            for (int p = 0; p < 2; p++) {
                t0 = fmaxf(t0, fmaxf(s[g][p][0], s[g][p][1]));
                t1 = fmaxf(t1, fmaxf(s[g][p][2], s[g][p][3]));
            }
        t0 = fmaxf(t0, __shfl_xor_sync(0xffffffffu, t0, 1));
        t0 = fmaxf(t0, __shfl_xor_sync(0xffffffffu, t0, 2));
        t1 = fmaxf(t1, __shfl_xor_sync(0xffffffffu, t1, 1));
        t1 = fmaxf(t1, __shfl_xor_sync(0xffffffffu, t1, 2));
        float mn0 = fmaxf(m0, t0), mn1 = fmaxf(m1, t1);
        float a0 = ex2f((m0 - mn0) * CEXP), a1 = ex2f((m1 - mn1) * CEXP);
        m0 = mn0; m1 = mn1;

        uint32_t pah[4][4], pal[4][4];
        float sum0 = 0.f, sum1 = 0.f;
#pragma unroll
        for (int g = 0; g < 4; g++)
#pragma unroll
            for (int p = 0; p < 2; p++) {
                float p0 = ex2f((s[g][p][0] - mn0) * CEXP);
                float p1 = ex2f((s[g][p][1] - mn0) * CEXP);
                float p2 = ex2f((s[g][p][2] - mn1) * CEXP);
                float p3 = ex2f((s[g][p][3] - mn1) * CEXP);
                sum0 += p0 + p1; sum1 += p2 + p3;
                pah[g][2 * p]     = pack2bf(p0, p1);
                pah[g][2 * p + 1] = pack2bf(p2, p3);
                pal[g][2 * p]     = pack2bf(p0 - bf_hi_f(p0), p1 - bf_hi_f(p1));
                pal[g][2 * p + 1] = pack2bf(p2 - bf_hi_f(p2), p3 - bf_hi_f(p3));
            }
        sum0 += __shfl_xor_sync(0xffffffffu, sum0, 1);
        sum0 += __shfl_xor_sync(0xffffffffu, sum0, 2);
        sum1 += __shfl_xor_sync(0xffffffffu, sum1, 1);
        sum1 += __shfl_xor_sync(0xffffffffu, sum1, 2);
        l0 = l0 * a0 + sum0;
        l1 = l1 * a1 + sum1;

#pragma unroll
        for (int gd = 0; gd < 8; gd++)
#pragma unroll
            for (int p = 0; p < 2; p++) {
                acc_o[gd][p][0] *= a0; acc_o[gd][p][1] *= a0;
                acc_o[gd][p][2] *= a1; acc_o[gd][p][3] *= a1;
            }

#pragma unroll
        for (int kc = 0; kc < 4; kc++)
#pragma unroll
            for (int gd = 0; gd < 8; gd++) {
                uint32_t off = (uint32_t)((gd * 16 + lr) * VTSTR + kc * 16 + lc) * 2;
                uint32_t bvh[4], bvl[4];
                ldsm_x4(vb_ + off, bvh[0], bvh[1], bvh[2], bvh[3]);
                ldsm_x4(vb_ + 18432 + off, bvl[0], bvl[1], bvl[2], bvl[3]);
                mma_bf16(acc_o[gd][0], pah[kc], bvh[0], bvh[2]);
                mma_bf16(acc_o[gd][1], pah[kc], bvh[1], bvh[3]);
                mma_bf16(acc_o[gd][0], pah[kc], bvl[0], bvl[2]);
                mma_bf16(acc_o[gd][1], pah[kc], bvl[1], bvl[3]);
                mma_bf16(acc_o[gd][0], pal[kc], bvh[0], bvh[2]);
                mma_bf16(acc_o[gd][1], pal[kc], bvh[1], bvh[3]);
            }
        __syncthreads();
    }

    const float i0 = 1.f / l0, i1 = 1.f / l1;
    const size_t tok0 = (size_t)b * SEQ + qb * 128 + wq0 + gr;
#pragma unroll
    for (int gd = 0; gd < 8; gd++)
#pragma unroll
        for (int p = 0; p < 2; p++) {
            int col = h * HD + gd * 16 + p * 8 + gc;
            float v0 = acc_o[gd][p][0] * i0, v1 = acc_o[gd][p][1] * i0;
            float v2 = acc_o[gd][p][2] * i1, v3 = acc_o[gd][p][3] * i1;
            size_t o0 = tok0 * DMODEL + col, o1 = (tok0 + 8) * DMODEL + col;
            *(uint32_t*)&ath[o0] = pack2bf(v0, v1);
            *(uint32_t*)&atl[o0] = pack2bf(v0 - bf_hi_f(v0), v1 - bf_hi_f(v1));
            *(uint32_t*)&ath[o1] = pack2bf(v2, v3);
            *(uint32_t*)&atl[o1] = pack2bf(v2 - bf_hi_f(v2), v3 - bf_hi_f(v3));
        }
}

// ---------------------------------------------------------------------------
extern "C" void kernel_launch(void* const* d_in, const int* in_sizes, int n_in,
                              void* d_out, int out_size)
{
    const float* x    = (const float*)d_in[0];
    const float* Wqkv = (const float*)d_in[1];
    const float* Wo   = (const float*)d_in[2];
    float* out = (float*)d_out;

    void* p;
    cudaGetSymbolAddress(&p, g_xh);    __nv_bfloat16* xh = (__nv_bfloat16*)p;
    cudaGetSymbolAddress(&p, g_xl);    __nv_bfloat16* xl = (__nv_bfloat16*)p;
    cudaGetSymbolAddress(&p, g_wqkvh); __nv_bfloat16* wqh = (__nv_bfloat16*)p;
    cudaGetSymbolAddress(&p, g_wqkvl); __nv_bfloat16* wql = (__nv_bfloat16*)p;
    cudaGetSymbolAddress(&p, g_woh);   __nv_bfloat16* woh = (__nv_bfloat16*)p;
    cudaGetSymbolAddress(&p, g_wol);   __nv_bfloat16* wol = (__nv_bfloat16*)p;
    cudaGetSymbolAddress(&p, g_qkvh);  __nv_bfloat16* qvh = (__nv_bfloat16*)p;
    cudaGetSymbolAddress(&p, g_vth);   __nv_bfloat16* vth = (__nv_bfloat16*)p;
    cudaGetSymbolAddress(&p, g_vtl);   __nv_bfloat16* vtl = (__nv_bfloat16*)p;
    cudaGetSymbolAddress(&p, g_ath);   __nv_bfloat16* ath = (__nv_bfloat16*)p;
    cudaGetSymbolAddress(&p, g_atl);   __nv_bfloat16* atl = (__nv_bfloat16*)p;

    cudaFuncSetAttribute(gemm_qkv, cudaFuncAttributeMaxDynamicSharedMemorySize,
                         GEMM3_SMEM);
    cudaFuncSetAttribute(gemm_out, cudaFuncAttributeMaxDynamicSharedMemorySize,
                         GEMM3_SMEM);
    cudaFuncSetAttribute(attn_mma, cudaFuncAttributeMaxDynamicSharedMemorySize,
                         ATTN_SMEM_BYTES);

    // 0) split inputs
    split_kernel<<<(NR * DMODEL / 4 + 255) / 256, 256>>>(x, xh, xl, NR * DMODEL / 4);
    split_kernel<<<(TDMODEL * DMODEL / 4 + 255) / 256, 256>>>(Wqkv, wqh, wql,
                                                              TDMODEL * DMODEL / 4);
    split_kernel<<<(DMODEL * DMODEL / 4 + 255) / 256, 256>>>(Wo, woh, wol,
                                                             DMODEL * DMODEL / 4);

    // 1) fused QKV projection: Q,K 1-pass (cols 0..4095), V 3-pass -> vt
    gemm_qkv<<<dim3(TDMODEL / 128, NR / 128), 256, GEMM3_SMEM>>>(
        xh, xl, wqh, wql, qvh, vth, vtl);

    // 2) attention -> bf16 hi/lo
    attn_mma<<<dim3(16, NH, NB), 256, ATTN_SMEM_BYTES>>>(qvh, vth, vtl, ath, atl);

    // 3) out = att @ Wo^T (fp32 out, 3-pass)
    gemm_out<<<dim3(DMODEL / 128, NR / 128), 256, GEMM3_SMEM>>>(
        ath, atl, woh, wol, out);
}

// round 12
// speedup vs baseline: 1.2030x; 1.2030x over previous
#include <cuda_runtime.h>
#include <cuda_bf16.h>
#include <math.h>
#include <stdint.h>

#define DMODEL 2048
#define TDMODEL 6144
#define NR 4096      // B*S rows
#define NH 16
#define HD 128
#define SEQ 2048
#define NB 2

// ---------------------------------------------------------------------------
// Scratch (no allocations allowed)
// ---------------------------------------------------------------------------
__device__ __nv_bfloat16 g_xh[(size_t)NR * DMODEL];
__device__ __nv_bfloat16 g_xl[(size_t)NR * DMODEL];
__device__ __nv_bfloat16 g_wqkvh[(size_t)TDMODEL * DMODEL];
__device__ __nv_bfloat16 g_wqkvl[(size_t)TDMODEL * DMODEL];
__device__ __nv_bfloat16 g_woh[(size_t)DMODEL * DMODEL];
__device__ __nv_bfloat16 g_wol[(size_t)DMODEL * DMODEL];
__device__ __nv_bfloat16 g_qkvh[(size_t)NR * TDMODEL];
__device__ __nv_bfloat16 g_qkvl[(size_t)NR * TDMODEL];
__device__ __nv_bfloat16 g_vth[(size_t)NB * NH * HD * SEQ];   // [b][h][d][tok]
__device__ __nv_bfloat16 g_vtl[(size_t)NB * NH * HD * SEQ];
__device__ __nv_bfloat16 g_ath[(size_t)NR * DMODEL];
__device__ __nv_bfloat16 g_atl[(size_t)NR * DMODEL];

// ---------------------------------------------------------------------------
// PTX helpers (sm_80+ portable)
// ---------------------------------------------------------------------------
__device__ __forceinline__ uint32_t smem_u32(const void* p) {
    uint32_t a;
    asm("{ .reg .u64 t; cvta.to.shared.u64 t, %1; cvt.u32.u64 %0, t; }" : "=r"(a) : "l"(p));
    return a;
}
__device__ __forceinline__ void cp16(uint32_t dst, const void* src) {
    asm volatile("cp.async.cg.shared.global [%0], [%1], 16;" :: "r"(dst), "l"(src));
}
__device__ __forceinline__ void ldsm_x4(uint32_t addr, uint32_t& r0, uint32_t& r1,
                                        uint32_t& r2, uint32_t& r3) {
    asm volatile("ldmatrix.sync.aligned.m8n8.x4.shared.b16 {%0,%1,%2,%3}, [%4];"
                 : "=r"(r0), "=r"(r1), "=r"(r2), "=r"(r3) : "r"(addr));
}
__device__ __forceinline__ void mma_bf16(float* d, const uint32_t* a,
                                         uint32_t b0, uint32_t b1) {
    asm volatile(
        "mma.sync.aligned.m16n8k16.row.col.f32.bf16.bf16.f32 "
        "{%0,%1,%2,%3}, {%4,%5,%6,%7}, {%8,%9}, {%0,%1,%2,%3};"
        : "+f"(d[0]), "+f"(d[1]), "+f"(d[2]), "+f"(d[3])
        : "r"(a[0]), "r"(a[1]), "r"(a[2]), "r"(a[3]), "r"(b0), "r"(b1));
}
__device__ __forceinline__ float ex2f(float x) {
    float y; asm("ex2.approx.f32 %0, %1;" : "=f"(y) : "f"(x)); return y;
}
// pack {lo, hi} fp32 -> bf16x2 (lo in bits [0:16))
__device__ __forceinline__ uint32_t pack2bf(float lo, float hi) {
    uint32_t r;
    asm("cvt.rn.bf16x2.f32 %0, %1, %2;" : "=r"(r) : "f"(hi), "f"(lo));
    return r;
}
__device__ __forceinline__ float bf_hi_f(float v) {
    return __bfloat162float(__float2bfloat16(v));
}
// swizzle for 64 B/row smem tiles: flips chunk bits [4:6) by row bits [7:9)
__device__ __forceinline__ uint32_t swz64(uint32_t o) {
    return o ^ (((o >> 7) & 3u) << 4);
}

// ---------------------------------------------------------------------------
// Split fp32 -> bf16 hi + bf16 lo (residual)
// ---------------------------------------------------------------------------
__global__ void split_kernel(const float* __restrict__ s,
                             __nv_bfloat16* __restrict__ h,
                             __nv_bfloat16* __restrict__ l, int n4)
{
    int i = blockIdx.x * blockDim.x + threadIdx.x;
    if (i >= n4) return;
    float4 v = ((const float4*)s)[i];
    uint2 uh, ul;
    uh.x = pack2bf(v.x, v.y);
    uh.y = pack2bf(v.z, v.w);
    ul.x = pack2bf(v.x - bf_hi_f(v.x), v.y - bf_hi_f(v.y));
    ul.y = pack2bf(v.z - bf_hi_f(v.z), v.w - bf_hi_f(v.w));
    ((uint2*)h)[i] = uh;
    ((uint2*)l)[i] = ul;
}

// ---------------------------------------------------------------------------
// V transpose: qkv[tok][4096 + h*128 + d] -> vt[(b,h)][d][tok]  (bf16 bits)
// ---------------------------------------------------------------------------
__global__ void vtrans_kernel(const ushort* __restrict__ qh, const ushort* __restrict__ ql,
                              ushort* __restrict__ vh, ushort* __restrict__ vl)
{
    __shared__ ushort t0[32][33], t1[32][33];
    const int bh = blockIdx.z, b = bh >> 4, h = bh & 15;
    const int tok0 = blockIdx.x * 32, d0 = blockIdx.y * 32;
    const int tx = threadIdx.x, ty = threadIdx.y;
    const size_t sbase = ((size_t)(b * SEQ + tok0)) * TDMODEL + 2 * DMODEL + h * HD + d0;
#pragma unroll
    for (int i = 0; i < 4; i++) {
        int r = ty + i * 8;
        t0[r][tx] = qh[sbase + (size_t)r * TDMODEL + tx];
        t1[r][tx] = ql[sbase + (size_t)r * TDMODEL + tx];
    }
    __syncthreads();
    const size_t dbase = ((size_t)(bh * HD + d0)) * SEQ + tok0;
#pragma unroll
    for (int i = 0; i < 4; i++) {
        int r = ty + i * 8;
        vh[dbase + (size_t)r * SEQ + tx] = t0[tx][r];
        vl[dbase + (size_t)r * SEQ + tx] = t1[tx][r];
    }
}

// ---------------------------------------------------------------------------
// mma.sync NT GEMM, NPASS = 1 (hi*hi) or 3 (hi*hi + hi*lo + lo*hi).
// 128x128 tile, BK=32, 8 warps (2x4), warp tile 64x32.
// NSTGK-stage cp.async ring, unrolled (stage offsets compile-time const);
// all ldsm/cp smem addresses precomputed. NPASS==1 epilogue writes hi only.
// ---------------------------------------------------------------------------
#define TS 8192u                         // 128 rows x 64 B per operand stage

template<bool SPLIT, int NPASS, int NSTGK>
__global__ __launch_bounds__(256, 2)
void gemm_mma(const __nv_bfloat16* __restrict__ Ah, const __nv_bfloat16* __restrict__ Al,
              const __nv_bfloat16* __restrict__ Bh, const __nv_bfloat16* __restrict__ Bl,
              float* __restrict__ C, __nv_bfloat16* __restrict__ Ch,
              __nv_bfloat16* __restrict__ Cl, int ldc, int K)
{
    constexpr uint32_t ALOFF = 2u * NSTGK * TS;   // hi -> lo operand base distance
    extern __shared__ char smem[];
    const uint32_t sb = (smem_u32(smem) + 1023u) & ~1023u;
    const uint32_t sAh = sb;
    const uint32_t sBh = sb + NSTGK * TS;

    const int tid = threadIdx.x, lane = tid & 31, wid = tid >> 5;
    const int bm = blockIdx.y * 128, bn = blockIdx.x * 128;
    const int m0 = (wid & 1) * 64, n0 = (wid >> 1) * 32;

    const char* gAh = (const char*)(Ah + (size_t)bm * K);
    const char* gAl = (const char*)(Al + (size_t)bm * K);
    const char* gBh = (const char*)(Bh + (size_t)bn * K);
    const char* gBl = (const char*)(Bl + (size_t)bn * K);

    float acc[4][4][4];
#pragma unroll
    for (int i = 0; i < 4; i++)
#pragma unroll
        for (int j = 0; j < 4; j++)
#pragma unroll
            for (int c = 0; c < 4; c++) acc[i][j][c] = 0.f;

    // ---- precomputed cp.async smem offsets ----
    const int lrow = tid >> 2;
    const int lch = (tid & 3) * 16;
    uint32_t cpRel[2], goRow[2];
#pragma unroll
    for (int t = 0; t < 2; t++) {
        cpRel[t] = swz64((uint32_t)((lrow + t * 64) * 64) + lch);
        goRow[t] = (uint32_t)((lrow + t * 64) * K * 2) + lch;
    }

    // ---- precomputed ldsm addresses (stage 0) ----
    const int lr = lane & 15;
    const uint32_t lcb = (uint32_t)((lane >> 4) * 16);
    uint32_t aAddr[4][2], bAddr[2][2];
#pragma unroll
    for (int mt = 0; mt < 4; mt++) {
        uint32_t row = (uint32_t)(m0 + mt * 16 + lr);
        uint32_t swz = ((row >> 1) & 3u) << 4;
#pragma unroll
        for (int ks = 0; ks < 2; ks++)
            aAddr[mt][ks] = sAh + row * 64 + (((uint32_t)(ks * 32) | lcb) ^ swz);
    }
#pragma unroll
    for (int g = 0; g < 2; g++) {
        uint32_t row = (uint32_t)(n0 + g * 16 + lr);
        uint32_t swz = ((row >> 1) & 3u) << 4;
#pragma unroll
        for (int ks = 0; ks < 2; ks++)
            bAddr[g][ks] = sBh + row * 64 + (((uint32_t)(ks * 32) | lcb) ^ swz);
    }

    auto load_stage = [&](int kb, uint32_t bufo) {
        const uint32_t gofs = (uint32_t)kb * 64;
#pragma unroll
        for (int t = 0; t < 2; t++) {
            uint32_t so = cpRel[t] + bufo;
            uint32_t go = goRow[t] + gofs;
            cp16(sAh + so, gAh + go);
            cp16(sBh + so, gBh + go);
            if (NPASS == 3) {
                cp16(sAh + ALOFF + so, gAl + go);
                cp16(sBh + ALOFF + so, gBl + go);
            }
        }
        asm volatile("cp.async.commit_group;" ::: "memory");
    };

    const int nk = K / 32;
#pragma unroll
    for (int s = 0; s < NSTGK - 1; s++) load_stage(s, (uint32_t)s * TS);

    for (int kb0 = 0; kb0 < nk; kb0 += NSTGK) {
#pragma unroll
        for (int u = 0; u < NSTGK; u++) {
            const int kb = kb0 + u;
            if (kb >= nk) break;
            asm volatile("cp.async.wait_group %0;" :: "n"(NSTGK - 2) : "memory");
            __syncthreads();
            {
                int nkb = kb + NSTGK - 1;
                const uint32_t nbufo = (uint32_t)((u + NSTGK - 1) % NSTGK) * TS;
                if (nkb < nk) load_stage(nkb, nbufo);
                else asm volatile("cp.async.commit_group;" ::: "memory");
            }
            const uint32_t bufo = (uint32_t)u * TS;

#pragma unroll
            for (int ks = 0; ks < 2; ks++) {
                uint32_t ah[4][4], al[4][4], bh[2][4], bl[2][4];
#pragma unroll
                for (int mt = 0; mt < 4; mt++) {
                    uint32_t addr = aAddr[mt][ks] + bufo;
                    ldsm_x4(addr, ah[mt][0], ah[mt][1], ah[mt][2], ah[mt][3]);
                    if (NPASS == 3)
                        ldsm_x4(addr + ALOFF, al[mt][0], al[mt][1], al[mt][2], al[mt][3]);
                }
#pragma unroll
                for (int g = 0; g < 2; g++) {
                    uint32_t addr = bAddr[g][ks] + bufo;
                    ldsm_x4(addr, bh[g][0], bh[g][1], bh[g][2], bh[g][3]);
                    if (NPASS == 3)
                        ldsm_x4(addr + ALOFF, bl[g][0], bl[g][1], bl[g][2], bl[g][3]);
                }
#pragma unroll
                for (int mt = 0; mt < 4; mt++)
#pragma unroll
                    for (int nt = 0; nt < 4; nt++) {
                        const int g = nt >> 1, p = nt & 1;
                        mma_bf16(acc[mt][nt], ah[mt], bh[g][p], bh[g][p + 2]);
                        if (NPASS == 3) {
                            mma_bf16(acc[mt][nt], ah[mt], bl[g][p], bl[g][p + 2]);
                            mma_bf16(acc[mt][nt], al[mt], bh[g][p], bh[g][p + 2]);
                        }
                    }
            }
        }
    }

    const int gr = lane >> 2, gc = (lane & 3) * 2;
#pragma unroll
    for (int mt = 0; mt < 4; mt++)
#pragma unroll
        for (int nt = 0; nt < 4; nt++) {
            int r = bm + m0 + mt * 16 + gr;
            int cix = bn + n0 + nt * 8 + gc;
            if (SPLIT) {
#pragma unroll
                for (int half = 0; half < 2; half++) {
                    float v0 = acc[mt][nt][half * 2], v1 = acc[mt][nt][half * 2 + 1];
                    size_t o = (size_t)(r + half * 8) * ldc + cix;
                    *(uint32_t*)&Ch[o] = pack2bf(v0, v1);
                    if (NPASS == 3)   // lo plane consumed only for V columns
                        *(uint32_t*)&Cl[o] = pack2bf(v0 - bf_hi_f(v0), v1 - bf_hi_f(v1));
                }
            } else {
                *(float2*)&C[(size_t)r * ldc + cix] =
                    make_float2(acc[mt][nt][0], acc[mt][nt][1]);
                *(float2*)&C[(size_t)(r + 8) * ldc + cix] =
                    make_float2(acc[mt][nt][2], acc[mt][nt][3]);
            }
        }
}

#define GEMM1_SMEM (2 * 4 * TS + 1024)         // 66560 (NSTG=4, 1-pass)
#define GEMM3_SMEM (4 * 3 * TS + 1024)         // 99328 (NSTG=3, 3-pass)

// ---------------------------------------------------------------------------
// Tensor-core causal flash attention (unchanged from R8).
// ---------------------------------------------------------------------------
#define QSTR 136
#define VTSTR 72
#define SM_Q 0
#define SM_K 34816
#define SM_VT 69632
#define ATTN_SMEM_BYTES 143360
#define CEXP 0.12751744f                 // log2(e)/sqrt(128)
#define MASKV (-1e30f)

__global__ __launch_bounds__(256, 1)
void attn_mma(const __nv_bfloat16* __restrict__ qkvh,
              const __nv_bfloat16* __restrict__ vth,
              const __nv_bfloat16* __restrict__ vtl,
              __nv_bfloat16* __restrict__ ath, __nv_bfloat16* __restrict__ atl)
{
    extern __shared__ char smem[];
    const uint32_t sb = smem_u32(smem);

    const int tid = threadIdx.x, lane = tid & 31, wid = tid >> 5;
    const int qb = 15 - blockIdx.x;
    const int h = blockIdx.y, b = blockIdx.z;
    const int wq0 = wid * 16;
    const int lr = lane & 15, lc = (lane >> 4) * 8;
    const int gr = lane >> 2, gc = (lane & 3) * 2;

    const char* gQ = (const char*)qkvh + ((size_t)(b * SEQ + qb * 128)) * (TDMODEL * 2)
                     + h * 256;
    const char* gK = (const char*)qkvh + ((size_t)(b * SEQ)) * (TDMODEL * 2)
                     + DMODEL * 2 + h * 256;
    const char* gVh = (const char*)vth + ((size_t)((b * NH + h) * HD)) * (SEQ * 2);
    const char* gVl = (const char*)vtl + ((size_t)((b * NH + h) * HD)) * (SEQ * 2);

    {
#pragma unroll
        for (int i = 0; i < 8; i++) {
            int c = tid + i * 256;
            int row = c >> 4, coff = (c & 15) * 16;
            cp16(sb + SM_Q + row * (QSTR * 2) + coff, gQ + (size_t)row * 12288 + coff);
        }
        asm volatile("cp.async.commit_group;" ::: "memory");
    }
    auto load_stage = [&](int kt, int buf) {
        const uint32_t kb_ = sb + SM_K + buf * 17408;
        const uint32_t vb_ = sb + SM_VT + buf * 36864;
#pragma unroll
        for (int i = 0; i < 4; i++) {
            int c = tid + i * 256;
            int row = c >> 4, coff = (c & 15) * 16;
            cp16(kb_ + row * (QSTR * 2) + coff,
                 gK + (size_t)(kt * 64 + row) * 12288 + coff);
        }
#pragma unroll
        for (int i = 0; i < 4; i++) {
            int c = tid + i * 256;
            int row = c >> 3, coff = (c & 7) * 16;
            size_t go = (size_t)row * (SEQ * 2) + (size_t)kt * 128 + coff;
            cp16(vb_ + row * (VTSTR * 2) + coff, gVh + go);
            cp16(vb_ + 18432 + row * (VTSTR * 2) + coff, gVl + go);
        }
        asm volatile("cp.async.commit_group;" ::: "memory");
    };
    load_stage(0, 0);

    uint32_t qf[8][4];
    float acc_o[8][2][4];
#pragma unroll
    for (int gd = 0; gd < 8; gd++)
#pragma unroll
        for (int p = 0; p < 2; p++)
#pragma unroll
            for (int c = 0; c < 4; c++) acc_o[gd][p][c] = 0.f;
    float m0 = MASKV, m1 = MASKV, l0 = 0.f, l1 = 0.f;

    const int ktmax = 2 * qb + 1;
    const int q_row0 = qb * 128 + wq0 + gr;

    for (int kt = 0; kt <= ktmax; kt++) {
        const int buf = kt & 1;
        if (kt < ktmax) {
            load_stage(kt + 1, buf ^ 1);
            asm volatile("cp.async.wait_group 1;" ::: "memory");
        } else {
            asm volatile("cp.async.wait_group 0;" ::: "memory");
        }
        __syncthreads();

        if (kt == 0) {
#pragma unroll
            for (int dc = 0; dc < 8; dc++) {
                uint32_t off = sb + SM_Q + (uint32_t)((wq0 + lr) * QSTR + dc * 16 + lc) * 2;
                ldsm_x4(off, qf[dc][0], qf[dc][1], qf[dc][2], qf[dc][3]);
            }
        }

        const uint32_t kb_ = sb + SM_K + buf * 17408;
        const uint32_t vb_ = sb + SM_VT + buf * 36864;

        float s[4][2][4];
#pragma unroll
        for (int g = 0; g < 4; g++)
#pragma unroll
            for (int p = 0; p < 2; p++)
#pragma unroll
                for (int c = 0; c < 4; c++) s[g][p][c] = 0.f;
#pragma unroll
        for (int dc = 0; dc < 8; dc++)
#pragma unroll
            for (int g = 0; g < 4; g++) {
                uint32_t kbt[4];
                ldsm_x4(kb_ + (uint32_t)((g * 16 + lr) * QSTR + dc * 16 + lc) * 2,
                        kbt[0], kbt[1], kbt[2], kbt[3]);
                mma_bf16(s[g][0], qf[dc], kbt[0], kbt[2]);
                mma_bf16(s[g][1], qf[dc], kbt[1], kbt[3]);
            }

        if (kt >= 2 * qb) {
#pragma unroll
            for (int g = 0; g < 4; g++)
#pragma unroll
                for (int p = 0; p < 2; p++) {
                    int key = kt * 64 + g * 16 + p * 8 + gc;
                    if (key > q_row0)     s[g][p][0] = MASKV;
                    if (key + 1 > q_row0) s[g][p][1] = MASKV;
                    if (key > q_row0 + 8)     s[g][p][2] = MASKV;
                    if (key + 1 > q_row0 + 8) s[g][p][3] = MASKV;
                }
        }

        float t0 = MASKV, t1 = MASKV;
#pragma unroll
        for (int g = 0; g < 4; g++)
#pragma unroll
            for (int p = 0; p < 2; p++) {
                t0 = fmaxf(t0, fmaxf(s[g][p][0], s[g][p][1]));
                t1 = fmaxf(t1, fmaxf(s[g][p][2], s[g][p][3]));
            }
        t0 = fmaxf(t0, __shfl_xor_sync(0xffffffffu, t0, 1));
        t0 = fmaxf(t0, __shfl_xor_sync(0xffffffffu, t0, 2));
        t1 = fmaxf(t1, __shfl_xor_sync(0xffffffffu, t1, 1));
        t1 = fmaxf(t1, __shfl_xor_sync(0xffffffffu, t1, 2));
        float mn0 = fmaxf(m0, t0), mn1 = fmaxf(m1, t1);
        float a0 = ex2f((m0 - mn0) * CEXP), a1 = ex2f((m1 - mn1) * CEXP);
        m0 = mn0; m1 = mn1;

        uint32_t pah[4][4], pal[4][4];
        float sum0 = 0.f, sum1 = 0.f;
#pragma unroll
        for (int g = 0; g < 4; g++)
#pragma unroll
            for (int p = 0; p < 2; p++) {
                float p0 = ex2f((s[g][p][0] - mn0) * CEXP);
                float p1 = ex2f((s[g][p][1] - mn0) * CEXP);
                float p2 = ex2f((s[g][p][2] - mn1) * CEXP);
                float p3 = ex2f((s[g][p][3] - mn1) * CEXP);
                sum0 += p0 + p1; sum1 += p2 + p3;
                pah[g][2 * p]     = pack2bf(p0, p1);
                pah[g][2 * p + 1] = pack2bf(p2, p3);
                pal[g][2 * p]     = pack2bf(p0 - bf_hi_f(p0), p1 - bf_hi_f(p1));
                pal[g][2 * p + 1] = pack2bf(p2 - bf_hi_f(p2), p3 - bf_hi_f(p3));
            }
        sum0 += __shfl_xor_sync(0xffffffffu, sum0, 1);
        sum0 += __shfl_xor_sync(0xffffffffu, sum0, 2);
        sum1 += __shfl_xor_sync(0xffffffffu, sum1, 1);
        sum1 += __shfl_xor_sync(0xffffffffu, sum1, 2);
        l0 = l0 * a0 + sum0;
        l1 = l1 * a1 + sum1;

#pragma unroll
        for (int gd = 0; gd < 8; gd++)
#pragma unroll
            for (int p = 0; p < 2; p++) {
                acc_o[gd][p][0] *= a0; acc_o[gd][p][1] *= a0;
                acc_o[gd][p][2] *= a1; acc_o[gd][p][3] *= a1;
            }

#pragma unroll
        for (int kc = 0; kc < 4; kc++)
#pragma unroll
            for (int gd = 0; gd < 8; gd++) {
                uint32_t off = (uint32_t)((gd * 16 + lr) * VTSTR + kc * 16 + lc) * 2;
                uint32_t bvh[4], bvl[4];
                ldsm_x4(vb_ + off, bvh[0], bvh[1], bvh[2], bvh[3]);
                ldsm_x4(vb_ + 18432 + off, bvl[0], bvl[1], bvl[2], bvl[3]);
                mma_bf16(acc_o[gd][0], pah[kc], bvh[0], bvh[2]);
                mma_bf16(acc_o[gd][1], pah[kc], bvh[1], bvh[3]);
                mma_bf16(acc_o[gd][0], pah[kc], bvl[0], bvl[2]);
                mma_bf16(acc_o[gd][1], pah[kc], bvl[1], bvl[3]);
                mma_bf16(acc_o[gd][0], pal[kc], bvh[0], bvh[2]);
                mma_bf16(acc_o[gd][1], pal[kc], bvh[1], bvh[3]);
            }
        __syncthreads();
    }

    const float i0 = 1.f / l0, i1 = 1.f / l1;
    const size_t tok0 = (size_t)b * SEQ + qb * 128 + wq0 + gr;
#pragma unroll
    for (int gd = 0; gd < 8; gd++)
#pragma unroll
        for (int p = 0; p < 2; p++) {
            int col = h * HD + gd * 16 + p * 8 + gc;
            float v0 = acc_o[gd][p][0] * i0, v1 = acc_o[gd][p][1] * i0;
            float v2 = acc_o[gd][p][2] * i1, v3 = acc_o[gd][p][3] * i1;
            size_t o0 = tok0 * DMODEL + col, o1 = (tok0 + 8) * DMODEL + col;
            *(uint32_t*)&ath[o0] = pack2bf(v0, v1);
            *(uint32_t*)&atl[o0] = pack2bf(v0 - bf_hi_f(v0), v1 - bf_hi_f(v1));
            *(uint32_t*)&ath[o1] = pack2bf(v2, v3);
            *(uint32_t*)&atl[o1] = pack2bf(v2 - bf_hi_f(v2), v3 - bf_hi_f(v3));
        }
}

// ---------------------------------------------------------------------------
extern "C" void kernel_launch(void* const* d_in, const int* in_sizes, int n_in,
                              void* d_out, int out_size)
{
    const float* x    = (const float*)d_in[0];
    const float* Wqkv = (const float*)d_in[1];
    const float* Wo   = (const float*)d_in[2];
    float* out = (float*)d_out;

    void* p;
    cudaGetSymbolAddress(&p, g_xh);    __nv_bfloat16* xh = (__nv_bfloat16*)p;
    cudaGetSymbolAddress(&p, g_xl);    __nv_bfloat16* xl = (__nv_bfloat16*)p;
    cudaGetSymbolAddress(&p, g_wqkvh); __nv_bfloat16* wqh = (__nv_bfloat16*)p;
    cudaGetSymbolAddress(&p, g_wqkvl); __nv_bfloat16* wql = (__nv_bfloat16*)p;
    cudaGetSymbolAddress(&p, g_woh);   __nv_bfloat16* woh = (__nv_bfloat16*)p;
    cudaGetSymbolAddress(&p, g_wol);   __nv_bfloat16* wol = (__nv_bfloat16*)p;
    cudaGetSymbolAddress(&p, g_qkvh);  __nv_bfloat16* qvh = (__nv_bfloat16*)p;
    cudaGetSymbolAddress(&p, g_qkvl);  __nv_bfloat16* qvl = (__nv_bfloat16*)p;
    cudaGetSymbolAddress(&p, g_vth);   __nv_bfloat16* vth = (__nv_bfloat16*)p;
    cudaGetSymbolAddress(&p, g_vtl);   __nv_bfloat16* vtl = (__nv_bfloat16*)p;
    cudaGetSymbolAddress(&p, g_ath);   __nv_bfloat16* ath = (__nv_bfloat16*)p;
    cudaGetSymbolAddress(&p, g_atl);   __nv_bfloat16* atl = (__nv_bfloat16*)p;

    cudaFuncSetAttribute(gemm_mma<true, 1, 4>,
                         cudaFuncAttributeMaxDynamicSharedMemorySize, GEMM1_SMEM);
    cudaFuncSetAttribute(gemm_mma<true, 3, 3>,
                         cudaFuncAttributeMaxDynamicSharedMemorySize, GEMM3_SMEM);
    cudaFuncSetAttribute(gemm_mma<false, 3, 3>,
                         cudaFuncAttributeMaxDynamicSharedMemorySize, GEMM3_SMEM);
    cudaFuncSetAttribute(attn_mma, cudaFuncAttributeMaxDynamicSharedMemorySize,
                         ATTN_SMEM_BYTES);

    // 0) split inputs
    split_kernel<<<(NR * DMODEL / 4 + 255) / 256, 256>>>(x, xh, xl, NR * DMODEL / 4);
    split_kernel<<<(TDMODEL * DMODEL / 4 + 255) / 256, 256>>>(Wqkv, wqh, wql,
                                                              TDMODEL * DMODEL / 4);
    split_kernel<<<(DMODEL * DMODEL / 4 + 255) / 256, 256>>>(Wo, woh, wol,
                                                             DMODEL * DMODEL / 4);

    // 1a) Q,K projection: single-pass bf16, hi-only output, 4-stage ring
    gemm_mma<true, 1, 4><<<dim3(2 * DMODEL / 128, NR / 128), 256, GEMM1_SMEM>>>(
        xh, xl, wqh, wql, nullptr, qvh, nullptr, TDMODEL, DMODEL);

    // 1b) V projection: 3-pass split
    gemm_mma<true, 3, 3><<<dim3(DMODEL / 128, NR / 128), 256, GEMM3_SMEM>>>(
        xh, xl, wqh + (size_t)2 * DMODEL * DMODEL, wql + (size_t)2 * DMODEL * DMODEL,
        nullptr, qvh + 2 * DMODEL, qvl + 2 * DMODEL, TDMODEL, DMODEL);

    // 2) transpose V panels
    vtrans_kernel<<<dim3(SEQ / 32, HD / 32, NB * NH), dim3(32, 8)>>>(
        (const ushort*)qvh, (const ushort*)qvl, (ushort*)vth, (ushort*)vtl);

    // 3) attention -> bf16 hi/lo
    attn_mma<<<dim3(16, NH, NB), 256, ATTN_SMEM_BYTES>>>(qvh, vth, vtl, ath, atl);

    // 4) out = att @ Wo^T (fp32 out, 3-pass)
    gemm_mma<false, 3, 3><<<dim3(DMODEL / 128, NR / 128), 256, GEMM3_SMEM>>>(
        ath, atl, woh, wol, out, nullptr, nullptr, DMODEL, DMODEL);
}

// round 13
// speedup vs baseline: 1.3400x; 1.1139x over previous
#include <cuda_runtime.h>
#include <cuda_bf16.h>
#include <math.h>
#include <stdint.h>

#define DMODEL 2048
#define TDMODEL 6144
#define NR 4096      // B*S rows
#define NH 16
#define HD 128
#define SEQ 2048
#define NB 2

// ---------------------------------------------------------------------------
// Scratch (no allocations allowed)
// ---------------------------------------------------------------------------
__device__ __nv_bfloat16 g_xh[(size_t)NR * DMODEL];
__device__ __nv_bfloat16 g_xl[(size_t)NR * DMODEL];
__device__ __nv_bfloat16 g_wqkvh[(size_t)TDMODEL * DMODEL];
__device__ __nv_bfloat16 g_wqkvl[(size_t)TDMODEL * DMODEL];
__device__ __nv_bfloat16 g_woh[(size_t)DMODEL * DMODEL];
__device__ __nv_bfloat16 g_wol[(size_t)DMODEL * DMODEL];
__device__ __nv_bfloat16 g_qkvh[(size_t)NR * TDMODEL];      // Q,K bf16; V cols fp16 bits
__device__ ushort g_vth[(size_t)NB * NH * HD * SEQ];        // fp16 bits [b][h][d][tok]
__device__ __nv_bfloat16 g_ath[(size_t)NR * DMODEL];
__device__ __nv_bfloat16 g_atl[(size_t)NR * DMODEL];

// ---------------------------------------------------------------------------
// PTX helpers (sm_80+ portable)
// ---------------------------------------------------------------------------
__device__ __forceinline__ uint32_t smem_u32(const void* p) {
    uint32_t a;
    asm("{ .reg .u64 t; cvta.to.shared.u64 t, %1; cvt.u32.u64 %0, t; }" : "=r"(a) : "l"(p));
    return a;
}
__device__ __forceinline__ void cp16(uint32_t dst, const void* src) {
    asm volatile("cp.async.cg.shared.global [%0], [%1], 16;" :: "r"(dst), "l"(src));
}
__device__ __forceinline__ void ldsm_x4(uint32_t addr, uint32_t& r0, uint32_t& r1,
                                        uint32_t& r2, uint32_t& r3) {
    asm volatile("ldmatrix.sync.aligned.m8n8.x4.shared.b16 {%0,%1,%2,%3}, [%4];"
                 : "=r"(r0), "=r"(r1), "=r"(r2), "=r"(r3) : "r"(addr));
}
__device__ __forceinline__ void mma_bf16(float* d, const uint32_t* a,
                                         uint32_t b0, uint32_t b1) {
    asm volatile(
        "mma.sync.aligned.m16n8k16.row.col.f32.bf16.bf16.f32 "
        "{%0,%1,%2,%3}, {%4,%5,%6,%7}, {%8,%9}, {%0,%1,%2,%3};"
        : "+f"(d[0]), "+f"(d[1]), "+f"(d[2]), "+f"(d[3])
        : "r"(a[0]), "r"(a[1]), "r"(a[2]), "r"(a[3]), "r"(b0), "r"(b1));
}
__device__ __forceinline__ void mma_f16(float* d, const uint32_t* a,
                                        uint32_t b0, uint32_t b1) {
    asm volatile(
        "mma.sync.aligned.m16n8k16.row.col.f32.f16.f16.f32 "
        "{%0,%1,%2,%3}, {%4,%5,%6,%7}, {%8,%9}, {%0,%1,%2,%3};"
        : "+f"(d[0]), "+f"(d[1]), "+f"(d[2]), "+f"(d[3])
        : "r"(a[0]), "r"(a[1]), "r"(a[2]), "r"(a[3]), "r"(b0), "r"(b1));
}
__device__ __forceinline__ float ex2f(float x) {
    float y; asm("ex2.approx.f32 %0, %1;" : "=f"(y) : "f"(x)); return y;
}
// pack {lo, hi} fp32 -> bf16x2 / f16x2 (lo in bits [0:16))
__device__ __forceinline__ uint32_t pack2bf(float lo, float hi) {
    uint32_t r;
    asm("cvt.rn.bf16x2.f32 %0, %1, %2;" : "=r"(r) : "f"(hi), "f"(lo));
    return r;
}
__device__ __forceinline__ uint32_t pack2h(float lo, float hi) {
    uint32_t r;
    asm("cvt.rn.f16x2.f32 %0, %1, %2;" : "=r"(r) : "f"(hi), "f"(lo));
    return r;
}
__device__ __forceinline__ float bf_hi_f(float v) {
    return __bfloat162float(__float2bfloat16(v));
}
// swizzle for 64 B/row smem tiles: flips chunk bits [4:6) by row bits [7:9)
__device__ __forceinline__ uint32_t swz64(uint32_t o) {
    return o ^ (((o >> 7) & 3u) << 4);
}

// ---------------------------------------------------------------------------
// Split fp32 -> bf16 hi + bf16 lo (residual)
// ---------------------------------------------------------------------------
__global__ void split_kernel(const float* __restrict__ s,
                             __nv_bfloat16* __restrict__ h,
                             __nv_bfloat16* __restrict__ l, int n4)
{
    int i = blockIdx.x * blockDim.x + threadIdx.x;
    if (i >= n4) return;
    float4 v = ((const float4*)s)[i];
    uint2 uh, ul;
    uh.x = pack2bf(v.x, v.y);
    uh.y = pack2bf(v.z, v.w);
    ul.x = pack2bf(v.x - bf_hi_f(v.x), v.y - bf_hi_f(v.y));
    ul.y = pack2bf(v.z - bf_hi_f(v.z), v.w - bf_hi_f(v.w));
    ((uint2*)h)[i] = uh;
    ((uint2*)l)[i] = ul;
}

// ---------------------------------------------------------------------------
// V transpose (single fp16 plane): qkv[tok][4096 + h*128 + d] -> vt[(b,h)][d][tok]
// ---------------------------------------------------------------------------
__global__ void vtrans_kernel(const ushort* __restrict__ qh, ushort* __restrict__ vh)
{
    __shared__ ushort t0[32][33];
    const int bh = blockIdx.z, b = bh >> 4, h = bh & 15;
    const int tok0 = blockIdx.x * 32, d0 = blockIdx.y * 32;
    const int tx = threadIdx.x, ty = threadIdx.y;
    const size_t sbase = ((size_t)(b * SEQ + tok0)) * TDMODEL + 2 * DMODEL + h * HD + d0;
#pragma unroll
    for (int i = 0; i < 4; i++) {
        int r = ty + i * 8;
        t0[r][tx] = qh[sbase + (size_t)r * TDMODEL + tx];
    }
    __syncthreads();
    const size_t dbase = ((size_t)(bh * HD + d0)) * SEQ + tok0;
#pragma unroll
    for (int i = 0; i < 4; i++) {
        int r = ty + i * 8;
        vh[dbase + (size_t)r * SEQ + tx] = t0[tx][r];
    }
}

// ---------------------------------------------------------------------------
// mma.sync NT GEMM. NPASS = 1 (hi*hi) or 3 (hi*hi + hi*lo + lo*hi).
// EMIT: 0 = fp32 -> C, 1 = bf16 hi/lo -> Ch/Cl, 2 = bf16 hi -> Ch,
//       3 = fp16 -> Ch (bits).
// 128x128 tile, BK=32, 8 warps (2x4), warp tile 64x32, NSTGK-stage ring.
// ---------------------------------------------------------------------------
#define TS 8192u                         // 128 rows x 64 B per operand stage

template<int EMIT, int NPASS, int NSTGK>
__global__ __launch_bounds__(256, 2)
void gemm_mma(const __nv_bfloat16* __restrict__ Ah, const __nv_bfloat16* __restrict__ Al,
              const __nv_bfloat16* __restrict__ Bh, const __nv_bfloat16* __restrict__ Bl,
              float* __restrict__ C, ushort* __restrict__ Ch,
              ushort* __restrict__ Cl, int ldc, int K)
{
    constexpr uint32_t ALOFF = 2u * NSTGK * TS;   // hi -> lo operand base distance
    extern __shared__ char smem[];
    const uint32_t sb = (smem_u32(smem) + 1023u) & ~1023u;
    const uint32_t sAh = sb;
    const uint32_t sBh = sb + NSTGK * TS;

    const int tid = threadIdx.x, lane = tid & 31, wid = tid >> 5;
    const int bm = blockIdx.y * 128, bn = blockIdx.x * 128;
    const int m0 = (wid & 1) * 64, n0 = (wid >> 1) * 32;

    const char* gAh = (const char*)(Ah + (size_t)bm * K);
    const char* gAl = (const char*)(Al + (size_t)bm * K);
    const char* gBh = (const char*)(Bh + (size_t)bn * K);
    const char* gBl = (const char*)(Bl + (size_t)bn * K);

    float acc[4][4][4];
#pragma unroll
    for (int i = 0; i < 4; i++)
#pragma unroll
        for (int j = 0; j < 4; j++)
#pragma unroll
            for (int c = 0; c < 4; c++) acc[i][j][c] = 0.f;

    // ---- precomputed cp.async smem offsets ----
    const int lrow = tid >> 2;
    const int lch = (tid & 3) * 16;
    uint32_t cpRel[2], goRow[2];
#pragma unroll
    for (int t = 0; t < 2; t++) {
        cpRel[t] = swz64((uint32_t)((lrow + t * 64) * 64) + lch);
        goRow[t] = (uint32_t)((lrow + t * 64) * K * 2) + lch;
    }

    // ---- precomputed ldsm addresses (stage 0) ----
    const int lr = lane & 15;
    const uint32_t lcb = (uint32_t)((lane >> 4) * 16);
    uint32_t aAddr[4][2], bAddr[2][2];
#pragma unroll
    for (int mt = 0; mt < 4; mt++) {
        uint32_t row = (uint32_t)(m0 + mt * 16 + lr);
        uint32_t swz = ((row >> 1) & 3u) << 4;
#pragma unroll
        for (int ks = 0; ks < 2; ks++)
            aAddr[mt][ks] = sAh + row * 64 + (((uint32_t)(ks * 32) | lcb) ^ swz);
    }
#pragma unroll
    for (int g = 0; g < 2; g++) {
        uint32_t row = (uint32_t)(n0 + g * 16 + lr);
        uint32_t swz = ((row >> 1) & 3u) << 4;
#pragma unroll
        for (int ks = 0; ks < 2; ks++)
            bAddr[g][ks] = sBh + row * 64 + (((uint32_t)(ks * 32) | lcb) ^ swz);
    }

    auto load_stage = [&](int kb, uint32_t bufo) {
        const uint32_t gofs = (uint32_t)kb * 64;
#pragma unroll
        for (int t = 0; t < 2; t++) {
            uint32_t so = cpRel[t] + bufo;
            uint32_t go = goRow[t] + gofs;
            cp16(sAh + so, gAh + go);
            cp16(sBh + so, gBh + go);
            if (NPASS == 3) {
                cp16(sAh + ALOFF + so, gAl + go);
                cp16(sBh + ALOFF + so, gBl + go);
            }
        }
        asm volatile("cp.async.commit_group;" ::: "memory");
    };

    const int nk = K / 32;
#pragma unroll
    for (int s = 0; s < NSTGK - 1; s++) load_stage(s, (uint32_t)s * TS);

    for (int kb0 = 0; kb0 < nk; kb0 += NSTGK) {
#pragma unroll
        for (int u = 0; u < NSTGK; u++) {
            const int kb = kb0 + u;
            if (kb >= nk) break;
            asm volatile("cp.async.wait_group %0;" :: "n"(NSTGK - 2) : "memory");
            __syncthreads();
            {
                int nkb = kb + NSTGK - 1;
                const uint32_t nbufo = (uint32_t)((u + NSTGK - 1) % NSTGK) * TS;
                if (nkb < nk) load_stage(nkb, nbufo);
                else asm volatile("cp.async.commit_group;" ::: "memory");
            }
            const uint32_t bufo = (uint32_t)u * TS;

#pragma unroll
            for (int ks = 0; ks < 2; ks++) {
                uint32_t ah[4][4], al[4][4], bh[2][4], bl[2][4];
#pragma unroll
                for (int mt = 0; mt < 4; mt++) {
                    uint32_t addr = aAddr[mt][ks] + bufo;
                    ldsm_x4(addr, ah[mt][0], ah[mt][1], ah[mt][2], ah[mt][3]);
                    if (NPASS == 3)
                        ldsm_x4(addr + ALOFF, al[mt][0], al[mt][1], al[mt][2], al[mt][3]);
                }
#pragma unroll
                for (int g = 0; g < 2; g++) {
                    uint32_t addr = bAddr[g][ks] + bufo;
                    ldsm_x4(addr, bh[g][0], bh[g][1], bh[g][2], bh[g][3]);
                    if (NPASS == 3)
                        ldsm_x4(addr + ALOFF, bl[g][0], bl[g][1], bl[g][2], bl[g][3]);
                }
#pragma unroll
                for (int mt = 0; mt < 4; mt++)
#pragma unroll
                    for (int nt = 0; nt < 4; nt++) {
                        const int g = nt >> 1, p = nt & 1;
                        mma_bf16(acc[mt][nt], ah[mt], bh[g][p], bh[g][p + 2]);
                        if (NPASS == 3) {
                            mma_bf16(acc[mt][nt], ah[mt], bl[g][p], bl[g][p + 2]);
                            mma_bf16(acc[mt][nt], al[mt], bh[g][p], bh[g][p + 2]);
                        }
                    }
            }
        }
    }

    const int gr = lane >> 2, gc = (lane & 3) * 2;
#pragma unroll
    for (int mt = 0; mt < 4; mt++)
#pragma unroll
        for (int nt = 0; nt < 4; nt++) {
            int r = bm + m0 + mt * 16 + gr;
            int cix = bn + n0 + nt * 8 + gc;
            if (EMIT == 0) {
                *(float2*)&C[(size_t)r * ldc + cix] =
                    make_float2(acc[mt][nt][0], acc[mt][nt][1]);
                *(float2*)&C[(size_t)(r + 8) * ldc + cix] =
                    make_float2(acc[mt][nt][2], acc[mt][nt][3]);
            } else {
#pragma unroll
                for (int half = 0; half < 2; half++) {
                    float v0 = acc[mt][nt][half * 2], v1 = acc[mt][nt][half * 2 + 1];
                    size_t o = (size_t)(r + half * 8) * ldc + cix;
                    if (EMIT == 3)
                        *(uint32_t*)&Ch[o] = pack2h(v0, v1);
                    else
                        *(uint32_t*)&Ch[o] = pack2bf(v0, v1);
                    if (EMIT == 1)
                        *(uint32_t*)&Cl[o] = pack2bf(v0 - bf_hi_f(v0), v1 - bf_hi_f(v1));
                }
            }
        }
}

#define GEMM1_SMEM (2 * 4 * TS + 1024)         // 66560 (NSTG=4, 1-pass)
#define GEMM3_SMEM (4 * 3 * TS + 1024)         // 99328 (NSTG=3, 3-pass)

// ---------------------------------------------------------------------------
// Tensor-core causal flash attention.
// QK: bf16 single-pass (unchanged). PV: single-pass fp16 (P fp16 x V fp16).
// ---------------------------------------------------------------------------
#define QSTR 136
#define VTSTR 72
#define SM_Q 0
#define SM_K 34816
#define SM_VT 69632
#define ATTN_SMEM_BYTES 106496           // 34816 Q + 2x17408 K + 2x18432 V
#define CEXP 0.12751744f                 // log2(e)/sqrt(128)
#define MASKV (-1e30f)

__global__ __launch_bounds__(256, 1)
void attn_mma(const __nv_bfloat16* __restrict__ qkvh,
              const ushort* __restrict__ vth,
              __nv_bfloat16* __restrict__ ath, __nv_bfloat16* __restrict__ atl)
{
    extern __shared__ char smem[];
    const uint32_t sb = smem_u32(smem);

    const int tid = threadIdx.x, lane = tid & 31, wid = tid >> 5;
    const int qb = 15 - blockIdx.x;
    const int h = blockIdx.y, b = blockIdx.z;
    const int wq0 = wid * 16;
    const int lr = lane & 15, lc = (lane >> 4) * 8;
    const int gr = lane >> 2, gc = (lane & 3) * 2;

    const char* gQ = (const char*)qkvh + ((size_t)(b * SEQ + qb * 128)) * (TDMODEL * 2)
                     + h * 256;
    const char* gK = (const char*)qkvh + ((size_t)(b * SEQ)) * (TDMODEL * 2)
                     + DMODEL * 2 + h * 256;
    const char* gVh = (const char*)vth + ((size_t)((b * NH + h) * HD)) * (SEQ * 2);

    {
#pragma unroll
        for (int i = 0; i < 8; i++) {
            int c = tid + i * 256;
            int row = c >> 4, coff = (c & 15) * 16;
            cp16(sb + SM_Q + row * (QSTR * 2) + coff, gQ + (size_t)row * 12288 + coff);
        }
        asm volatile("cp.async.commit_group;" ::: "memory");
    }
    auto load_stage = [&](int kt, int buf) {
        const uint32_t kb_ = sb + SM_K + buf * 17408;
        const uint32_t vb_ = sb + SM_VT + buf * 18432;
#pragma unroll
        for (int i = 0; i < 4; i++) {
            int c = tid + i * 256;
            int row = c >> 4, coff = (c & 15) * 16;
            cp16(kb_ + row * (QSTR * 2) + coff,
                 gK + (size_t)(kt * 64 + row) * 12288 + coff);
        }
#pragma unroll
        for (int i = 0; i < 4; i++) {
            int c = tid + i * 256;
            int row = c >> 3, coff = (c & 7) * 16;
            size_t go = (size_t)row * (SEQ * 2) + (size_t)kt * 128 + coff;
            cp16(vb_ + row * (VTSTR * 2) + coff, gVh + go);
        }
        asm volatile("cp.async.commit_group;" ::: "memory");
    };
    load_stage(0, 0);

    uint32_t qf[8][4];
    float acc_o[8][2][4];
#pragma unroll
    for (int gd = 0; gd < 8; gd++)
#pragma unroll
        for (int p = 0; p < 2; p++)
#pragma unroll
            for (int c = 0; c < 4; c++) acc_o[gd][p][c] = 0.f;
    float m0 = MASKV, m1 = MASKV, l0 = 0.f, l1 = 0.f;

    const int ktmax = 2 * qb + 1;
    const int q_row0 = qb * 128 + wq0 + gr;

    for (int kt = 0; kt <= ktmax; kt++) {
        const int buf = kt & 1;
        if (kt < ktmax) {
            load_stage(kt + 1, buf ^ 1);
            asm volatile("cp.async.wait_group 1;" ::: "memory");
        } else {
            asm volatile("cp.async.wait_group 0;" ::: "memory");
        }
        __syncthreads();

        if (kt == 0) {
#pragma unroll
            for (int dc = 0; dc < 8; dc++) {
                uint32_t off = sb + SM_Q + (uint32_t)((wq0 + lr) * QSTR + dc * 16 + lc) * 2;
                ldsm_x4(off, qf[dc][0], qf[dc][1], qf[dc][2], qf[dc][3]);
            }
        }

        const uint32_t kb_ = sb + SM_K + buf * 17408;
        const uint32_t vb_ = sb + SM_VT + buf * 18432;

        float s[4][2][4];
#pragma unroll
        for (int g = 0; g < 4; g++)
#pragma unroll
            for (int p = 0; p < 2; p++)
#pragma unroll
                for (int c = 0; c < 4; c++) s[g][p][c] = 0.f;
#pragma unroll
        for (int dc = 0; dc < 8; dc++)
#pragma unroll
            for (int g = 0; g < 4; g++) {
                uint32_t kbt[4];
                ldsm_x4(kb_ + (uint32_t)((g * 16 + lr) * QSTR + dc * 16 + lc) * 2,
                        kbt[0], kbt[1], kbt[2], kbt[3]);
                mma_bf16(s[g][0], qf[dc], kbt[0], kbt[2]);
                mma_bf16(s[g][1], qf[dc], kbt[1], kbt[3]);
            }

        if (kt >= 2 * qb) {
#pragma unroll
            for (int g = 0; g < 4; g++)
#pragma unroll
                for (int p = 0; p < 2; p++) {
                    int key = kt * 64 + g * 16 + p * 8 + gc;
                    if (key > q_row0)     s[g][p][0] = MASKV;
                    if (key + 1 > q_row0) s[g][p][1] = MASKV;
                    if (key > q_row0 + 8)     s[g][p][2] = MASKV;
                    if (key + 1 > q_row0 + 8) s[g][p][3] = MASKV;
                }
        }

        float t0 = MASKV, t1 = MASKV;
#pragma unroll
        for (int g = 0; g < 4; g++)
#pragma unroll
            for (int p = 0; p < 2; p++) {
                t0 = fmaxf(t0, fmaxf(s[g][p][0], s[g][p][1]));
                t1 = fmaxf(t1, fmaxf(s[g][p][2], s[g][p][3]));
            }
        t0 = fmaxf(t0, __shfl_xor_sync(0xffffffffu, t0, 1));
        t0 = fmaxf(t0, __shfl_xor_sync(0xffffffffu, t0, 2));
        t1 = fmaxf(t1, __shfl_xor_sync(0xffffffffu, t1, 1));
        t1 = fmaxf(t1, __shfl_xor_sync(0xffffffffu, t1, 2));
        float mn0 = fmaxf(m0, t0), mn1 = fmaxf(m1, t1);
        float a0 = ex2f((m0 - mn0) * CEXP), a1 = ex2f((m1 - mn1) * CEXP);
        m0 = mn0; m1 = mn1;

        uint32_t pah[4][4];
        float sum0 = 0.f, sum1 = 0.f;
#pragma unroll
        for (int g = 0; g < 4; g++)
#pragma unroll
            for (int p = 0; p < 2; p++) {
                float p0 = ex2f((s[g][p][0] - mn0) * CEXP);
                float p1 = ex2f((s[g][p][1] - mn0) * CEXP);
                float p2 = ex2f((s[g][p][2] - mn1) * CEXP);
                float p3 = ex2f((s[g][p][3] - mn1) * CEXP);
                sum0 += p0 + p1; sum1 += p2 + p3;
                pah[g][2 * p]     = pack2h(p0, p1);
                pah[g][2 * p + 1] = pack2h(p2, p3);
            }
        sum0 += __shfl_xor_sync(0xffffffffu, sum0, 1);
        sum0 += __shfl_xor_sync(0xffffffffu, sum0, 2);
        sum1 += __shfl_xor_sync(0xffffffffu, sum1, 1);
        sum1 += __shfl_xor_sync(0xffffffffu, sum1, 2);
        l0 = l0 * a0 + sum0;
        l1 = l1 * a1 + sum1;

#pragma unroll
        for (int gd = 0; gd < 8; gd++)
#pragma unroll
            for (int p = 0; p < 2; p++) {
                acc_o[gd][p][0] *= a0; acc_o[gd][p][1] *= a0;
                acc_o[gd][p][2] *= a1; acc_o[gd][p][3] *= a1;
            }

        // ---- O += P V  (single-pass fp16) ----
#pragma unroll
        for (int kc = 0; kc < 4; kc++)
#pragma unroll
            for (int gd = 0; gd < 8; gd++) {
                uint32_t off = (uint32_t)((gd * 16 + lr) * VTSTR + kc * 16 + lc) * 2;
                uint32_t bvh[4];
                ldsm_x4(vb_ + off, bvh[0], bvh[1], bvh[2], bvh[3]);
                mma_f16(acc_o[gd][0], pah[kc], bvh[0], bvh[2]);
                mma_f16(acc_o[gd][1], pah[kc], bvh[1], bvh[3]);
            }
        __syncthreads();
    }

    const float i0 = 1.f / l0, i1 = 1.f / l1;
    const size_t tok0 = (size_t)b * SEQ + qb * 128 + wq0 + gr;
#pragma unroll
    for (int gd = 0; gd < 8; gd++)
#pragma unroll
        for (int p = 0; p < 2; p++) {
            int col = h * HD + gd * 16 + p * 8 + gc;
            float v0 = acc_o[gd][p][0] * i0, v1 = acc_o[gd][p][1] * i0;
            float v2 = acc_o[gd][p][2] * i1, v3 = acc_o[gd][p][3] * i1;
            size_t o0 = tok0 * DMODEL + col, o1 = (tok0 + 8) * DMODEL + col;
            *(uint32_t*)&ath[o0] = pack2bf(v0, v1);
            *(uint32_t*)&atl[o0] = pack2bf(v0 - bf_hi_f(v0), v1 - bf_hi_f(v1));
            *(uint32_t*)&ath[o1] = pack2bf(v2, v3);
            *(uint32_t*)&atl[o1] = pack2bf(v2 - bf_hi_f(v2), v3 - bf_hi_f(v3));
        }
}

// ---------------------------------------------------------------------------
extern "C" void kernel_launch(void* const* d_in, const int* in_sizes, int n_in,
                              void* d_out, int out_size)
{
    const float* x    = (const float*)d_in[0];
    const float* Wqkv = (const float*)d_in[1];
    const float* Wo   = (const float*)d_in[2];
    float* out = (float*)d_out;

    void* p;
    cudaGetSymbolAddress(&p, g_xh);    __nv_bfloat16* xh = (__nv_bfloat16*)p;
    cudaGetSymbolAddress(&p, g_xl);    __nv_bfloat16* xl = (__nv_bfloat16*)p;
    cudaGetSymbolAddress(&p, g_wqkvh); __nv_bfloat16* wqh = (__nv_bfloat16*)p;
    cudaGetSymbolAddress(&p, g_wqkvl); __nv_bfloat16* wql = (__nv_bfloat16*)p;
    cudaGetSymbolAddress(&p, g_woh);   __nv_bfloat16* woh = (__nv_bfloat16*)p;
    cudaGetSymbolAddress(&p, g_wol);   __nv_bfloat16* wol = (__nv_bfloat16*)p;
    cudaGetSymbolAddress(&p, g_qkvh);  __nv_bfloat16* qvh = (__nv_bfloat16*)p;
    cudaGetSymbolAddress(&p, g_vth);   ushort* vth = (ushort*)p;
    cudaGetSymbolAddress(&p, g_ath);   __nv_bfloat16* ath = (__nv_bfloat16*)p;
    cudaGetSymbolAddress(&p, g_atl);   __nv_bfloat16* atl = (__nv_bfloat16*)p;

    cudaFuncSetAttribute(gemm_mma<2, 1, 4>,
                         cudaFuncAttributeMaxDynamicSharedMemorySize, GEMM1_SMEM);
    cudaFuncSetAttribute(gemm_mma<3, 3, 3>,
                         cudaFuncAttributeMaxDynamicSharedMemorySize, GEMM3_SMEM);
    cudaFuncSetAttribute(gemm_mma<0, 3, 3>,
                         cudaFuncAttributeMaxDynamicSharedMemorySize, GEMM3_SMEM);
    cudaFuncSetAttribute(attn_mma, cudaFuncAttributeMaxDynamicSharedMemorySize,
                         ATTN_SMEM_BYTES);

    // 0) split inputs
    split_kernel<<<(NR * DMODEL / 4 + 255) / 256, 256>>>(x, xh, xl, NR * DMODEL / 4);
    split_kernel<<<(TDMODEL * DMODEL / 4 + 255) / 256, 256>>>(Wqkv, wqh, wql,
                                                              TDMODEL * DMODEL / 4);
    split_kernel<<<(DMODEL * DMODEL / 4 + 255) / 256, 256>>>(Wo, woh, wol,
                                                             DMODEL * DMODEL / 4);

    // 1a) Q,K projection: single-pass bf16, hi-only output, 4-stage ring
    gemm_mma<2, 1, 4><<<dim3(2 * DMODEL / 128, NR / 128), 256, GEMM1_SMEM>>>(
        xh, xl, wqh, wql, nullptr, (ushort*)qvh, nullptr, TDMODEL, DMODEL);

    // 1b) V projection: 3-pass compute, fp16 single-plane output (into qkv V cols)
    gemm_mma<3, 3, 3><<<dim3(DMODEL / 128, NR / 128), 256, GEMM3_SMEM>>>(
        xh, xl, wqh + (size_t)2 * DMODEL * DMODEL, wql + (size_t)2 * DMODEL * DMODEL,
        nullptr, (ushort*)qvh + 2 * DMODEL, nullptr, TDMODEL, DMODEL);

    // 2) transpose V panel (fp16 bits, single plane)
    vtrans_kernel<<<dim3(SEQ / 32, HD / 32, NB * NH), dim3(32, 8)>>>(
        (const ushort*)qvh, vth);

    // 3) attention -> bf16 hi/lo
    attn_mma<<<dim3(16, NH, NB), 256, ATTN_SMEM_BYTES>>>(qvh, vth, ath, atl);

    // 4) out = att @ Wo^T (fp32 out, 3-pass)
    gemm_mma<0, 3, 3><<<dim3(DMODEL / 128, NR / 128), 256, GEMM3_SMEM>>>(
        ath, atl, woh, wol, out, nullptr, nullptr, DMODEL, DMODEL);
}

// round 14
// speedup vs baseline: 2.2176x; 1.6549x over previous
#include <cuda_runtime.h>
#include <cuda_bf16.h>
#include <math.h>
#include <stdint.h>

#define DMODEL 2048
#define TDMODEL 6144
#define NR 4096      // B*S rows
#define NH 16
#define HD 128
#define SEQ 2048
#define NB 2

// ---------------------------------------------------------------------------
// Scratch (no allocations allowed) — fp16 bit-planes
// ---------------------------------------------------------------------------
__device__ ushort g_xh[(size_t)NR * DMODEL];
__device__ ushort g_wqkvh[(size_t)TDMODEL * DMODEL];
__device__ ushort g_woh[(size_t)DMODEL * DMODEL];
__device__ ushort g_qkvh[(size_t)NR * TDMODEL];       // q,k,v all fp16
__device__ ushort g_vth[(size_t)NB * NH * HD * SEQ];  // [b][h][d][tok]
__device__ ushort g_ath[(size_t)NR * DMODEL];

// ---------------------------------------------------------------------------
// PTX helpers (sm_80+ portable)
// ---------------------------------------------------------------------------
__device__ __forceinline__ uint32_t smem_u32(const void* p) {
    uint32_t a;
    asm("{ .reg .u64 t; cvta.to.shared.u64 t, %1; cvt.u32.u64 %0, t; }" : "=r"(a) : "l"(p));
    return a;
}
__device__ __forceinline__ void cp16(uint32_t dst, const void* src) {
    asm volatile("cp.async.cg.shared.global [%0], [%1], 16;" :: "r"(dst), "l"(src));
}
__device__ __forceinline__ void ldsm_x4(uint32_t addr, uint32_t& r0, uint32_t& r1,
                                        uint32_t& r2, uint32_t& r3) {
    asm volatile("ldmatrix.sync.aligned.m8n8.x4.shared.b16 {%0,%1,%2,%3}, [%4];"
                 : "=r"(r0), "=r"(r1), "=r"(r2), "=r"(r3) : "r"(addr));
}
__device__ __forceinline__ void mma_f16(float* d, const uint32_t* a,
                                        uint32_t b0, uint32_t b1) {
    asm volatile(
        "mma.sync.aligned.m16n8k16.row.col.f32.f16.f16.f32 "
        "{%0,%1,%2,%3}, {%4,%5,%6,%7}, {%8,%9}, {%0,%1,%2,%3};"
        : "+f"(d[0]), "+f"(d[1]), "+f"(d[2]), "+f"(d[3])
        : "r"(a[0]), "r"(a[1]), "r"(a[2]), "r"(a[3]), "r"(b0), "r"(b1));
}
__device__ __forceinline__ float ex2f(float x) {
    float y; asm("ex2.approx.f32 %0, %1;" : "=f"(y) : "f"(x)); return y;
}
// pack {lo, hi} fp32 -> f16x2 (lo in bits [0:16))
__device__ __forceinline__ uint32_t pack2h(float lo, float hi) {
    uint32_t r;
    asm("cvt.rn.f16x2.f32 %0, %1, %2;" : "=r"(r) : "f"(hi), "f"(lo));
    return r;
}
// swizzle for 64 B/row smem tiles: flips chunk bits [4:6) by row bits [7:9)
__device__ __forceinline__ uint32_t swz64(uint32_t o) {
    return o ^ (((o >> 7) & 3u) << 4);
}

// ---------------------------------------------------------------------------
// Convert fp32 -> fp16
// ---------------------------------------------------------------------------
__global__ void cvt_kernel(const float* __restrict__ s, ushort* __restrict__ h, int n4)
{
    int i = blockIdx.x * blockDim.x + threadIdx.x;
    if (i >= n4) return;
    float4 v = ((const float4*)s)[i];
    uint2 uh;
    uh.x = pack2h(v.x, v.y);
    uh.y = pack2h(v.z, v.w);
    ((uint2*)h)[i] = uh;
}

// ---------------------------------------------------------------------------
// V transpose (fp16 bits): qkv[tok][4096 + h*128 + d] -> vt[(b,h)][d][tok]
// ---------------------------------------------------------------------------
__global__ void vtrans_kernel(const ushort* __restrict__ qh, ushort* __restrict__ vh)
{
    __shared__ ushort t0[32][33];
    const int bh = blockIdx.z, b = bh >> 4, h = bh & 15;
    const int tok0 = blockIdx.x * 32, d0 = blockIdx.y * 32;
    const int tx = threadIdx.x, ty = threadIdx.y;
    const size_t sbase = ((size_t)(b * SEQ + tok0)) * TDMODEL + 2 * DMODEL + h * HD + d0;
#pragma unroll
    for (int i = 0; i < 4; i++) {
        int r = ty + i * 8;
        t0[r][tx] = qh[sbase + (size_t)r * TDMODEL + tx];
    }
    __syncthreads();
    const size_t dbase = ((size_t)(bh * HD + d0)) * SEQ + tok0;
#pragma unroll
    for (int i = 0; i < 4; i++) {
        int r = ty + i * 8;
        vh[dbase + (size_t)r * SEQ + tx] = t0[tx][r];
    }
}

// ---------------------------------------------------------------------------
// mma.sync NT GEMM, single-pass fp16, fp32 accumulate.
// EMIT: 0 = fp32 -> C, 1 = fp16 -> Ch.
// 128x128 tile, BK=32, 8 warps (2x4), warp tile 64x32, 4-stage ring.
// ---------------------------------------------------------------------------
#define TS 8192u                         // 128 rows x 64 B per operand stage
#define NSTG 4
#define GEMM_SMEM (2 * NSTG * TS + 1024) // 66560

template<int EMIT>
__global__ __launch_bounds__(256, 2)
void gemm_f16(const ushort* __restrict__ A, const ushort* __restrict__ B,
              float* __restrict__ C, ushort* __restrict__ Ch, int ldc, int K)
{
    extern __shared__ char smem[];
    const uint32_t sb = (smem_u32(smem) + 1023u) & ~1023u;
    const uint32_t sA = sb;
    const uint32_t sB = sb + NSTG * TS;

    const int tid = threadIdx.x, lane = tid & 31, wid = tid >> 5;
    const int bm = blockIdx.y * 128, bn = blockIdx.x * 128;
    const int m0 = (wid & 1) * 64, n0 = (wid >> 1) * 32;

    const char* gA = (const char*)(A + (size_t)bm * K);
    const char* gB = (const char*)(B + (size_t)bn * K);

    float acc[4][4][4];
#pragma unroll
    for (int i = 0; i < 4; i++)
#pragma unroll
        for (int j = 0; j < 4; j++)
#pragma unroll
            for (int c = 0; c < 4; c++) acc[i][j][c] = 0.f;

    const int lrow = tid >> 2;
    const int lch = (tid & 3) * 16;
    uint32_t cpRel[2], goRow[2];
#pragma unroll
    for (int t = 0; t < 2; t++) {
        cpRel[t] = swz64((uint32_t)((lrow + t * 64) * 64) + lch);
        goRow[t] = (uint32_t)((lrow + t * 64) * K * 2) + lch;
    }

    const int lr = lane & 15;
    const uint32_t lcb = (uint32_t)((lane >> 4) * 16);
    uint32_t aAddr[4][2], bAddr[2][2];
#pragma unroll
    for (int mt = 0; mt < 4; mt++) {
        uint32_t row = (uint32_t)(m0 + mt * 16 + lr);
        uint32_t swz = ((row >> 1) & 3u) << 4;
#pragma unroll
        for (int ks = 0; ks < 2; ks++)
            aAddr[mt][ks] = sA + row * 64 + (((uint32_t)(ks * 32) | lcb) ^ swz);
    }
#pragma unroll
    for (int g = 0; g < 2; g++) {
        uint32_t row = (uint32_t)(n0 + g * 16 + lr);
        uint32_t swz = ((row >> 1) & 3u) << 4;
#pragma unroll
        for (int ks = 0; ks < 2; ks++)
            bAddr[g][ks] = sB + row * 64 + (((uint32_t)(ks * 32) | lcb) ^ swz);
    }

    auto load_stage = [&](int kb, uint32_t bufo) {
        const uint32_t gofs = (uint32_t)kb * 64;
#pragma unroll
        for (int t = 0; t < 2; t++) {
            uint32_t so = cpRel[t] + bufo;
            uint32_t go = goRow[t] + gofs;
            cp16(sA + so, gA + go);
            cp16(sB + so, gB + go);
        }
        asm volatile("cp.async.commit_group;" ::: "memory");
    };

    const int nk = K / 32;
#pragma unroll
    for (int s = 0; s < NSTG - 1; s++) load_stage(s, (uint32_t)s * TS);

    for (int kb0 = 0; kb0 < nk; kb0 += NSTG) {
#pragma unroll
        for (int u = 0; u < NSTG; u++) {
            const int kb = kb0 + u;
            if (kb >= nk) break;
            asm volatile("cp.async.wait_group %0;" :: "n"(NSTG - 2) : "memory");
            __syncthreads();
            {
                int nkb = kb + NSTG - 1;
                const uint32_t nbufo = (uint32_t)((u + NSTG - 1) % NSTG) * TS;
                if (nkb < nk) load_stage(nkb, nbufo);
                else asm volatile("cp.async.commit_group;" ::: "memory");
            }
            const uint32_t bufo = (uint32_t)u * TS;

#pragma unroll
            for (int ks = 0; ks < 2; ks++) {
                uint32_t ah[4][4], bh[2][4];
#pragma unroll
                for (int mt = 0; mt < 4; mt++)
                    ldsm_x4(aAddr[mt][ks] + bufo,
                            ah[mt][0], ah[mt][1], ah[mt][2], ah[mt][3]);
#pragma unroll
                for (int g = 0; g < 2; g++)
                    ldsm_x4(bAddr[g][ks] + bufo,
                            bh[g][0], bh[g][1], bh[g][2], bh[g][3]);
#pragma unroll
                for (int mt = 0; mt < 4; mt++)
#pragma unroll
                    for (int nt = 0; nt < 4; nt++) {
                        const int g = nt >> 1, p = nt & 1;
                        mma_f16(acc[mt][nt], ah[mt], bh[g][p], bh[g][p + 2]);
                    }
            }
        }
    }

    const int gr = lane >> 2, gc = (lane & 3) * 2;
#pragma unroll
    for (int mt = 0; mt < 4; mt++)
#pragma unroll
        for (int nt = 0; nt < 4; nt++) {
            int r = bm + m0 + mt * 16 + gr;
            int cix = bn + n0 + nt * 8 + gc;
            if (EMIT == 0) {
                *(float2*)&C[(size_t)r * ldc + cix] =
                    make_float2(acc[mt][nt][0], acc[mt][nt][1]);
                *(float2*)&C[(size_t)(r + 8) * ldc + cix] =
                    make_float2(acc[mt][nt][2], acc[mt][nt][3]);
            } else {
                *(uint32_t*)&Ch[(size_t)r * ldc + cix] =
                    pack2h(acc[mt][nt][0], acc[mt][nt][1]);
                *(uint32_t*)&Ch[(size_t)(r + 8) * ldc + cix] =
                    pack2h(acc[mt][nt][2], acc[mt][nt][3]);
            }
        }
}

// ---------------------------------------------------------------------------
// Tensor-core causal flash attention, all-fp16 operands, fp32 accum/softmax.
// ---------------------------------------------------------------------------
#define QSTR 136
#define VTSTR 72
#define SM_Q 0
#define SM_K 34816
#define SM_VT 69632
#define ATTN_SMEM_BYTES 106496           // 34816 Q + 2x17408 K + 2x18432 V
#define CEXP 0.12751744f                 // log2(e)/sqrt(128)
#define MASKV (-1e30f)

__global__ __launch_bounds__(256, 1)
void attn_mma(const ushort* __restrict__ qkvh,
              const ushort* __restrict__ vth,
              ushort* __restrict__ ath)
{
    extern __shared__ char smem[];
    const uint32_t sb = smem_u32(smem);

    const int tid = threadIdx.x, lane = tid & 31, wid = tid >> 5;
    const int qb = 15 - blockIdx.x;
    const int h = blockIdx.y, b = blockIdx.z;
    const int wq0 = wid * 16;
    const int lr = lane & 15, lc = (lane >> 4) * 8;
    const int gr = lane >> 2, gc = (lane & 3) * 2;

    const char* gQ = (const char*)qkvh + ((size_t)(b * SEQ + qb * 128)) * (TDMODEL * 2)
                     + h * 256;
    const char* gK = (const char*)qkvh + ((size_t)(b * SEQ)) * (TDMODEL * 2)
                     + DMODEL * 2 + h * 256;
    const char* gVh = (const char*)vth + ((size_t)((b * NH + h) * HD)) * (SEQ * 2);

    {
#pragma unroll
        for (int i = 0; i < 8; i++) {
            int c = tid + i * 256;
            int row = c >> 4, coff = (c & 15) * 16;
            cp16(sb + SM_Q + row * (QSTR * 2) + coff, gQ + (size_t)row * 12288 + coff);
        }
        asm volatile("cp.async.commit_group;" ::: "memory");
    }
    auto load_stage = [&](int kt, int buf) {
        const uint32_t kb_ = sb + SM_K + buf * 17408;
        const uint32_t vb_ = sb + SM_VT + buf * 18432;
#pragma unroll
        for (int i = 0; i < 4; i++) {
            int c = tid + i * 256;
            int row = c >> 4, coff = (c & 15) * 16;
            cp16(kb_ + row * (QSTR * 2) + coff,
                 gK + (size_t)(kt * 64 + row) * 12288 + coff);
        }
#pragma unroll
        for (int i = 0; i < 4; i++) {
            int c = tid + i * 256;
            int row = c >> 3, coff = (c & 7) * 16;
            size_t go = (size_t)row * (SEQ * 2) + (size_t)kt * 128 + coff;
            cp16(vb_ + row * (VTSTR * 2) + coff, gVh + go);
        }
        asm volatile("cp.async.commit_group;" ::: "memory");
    };
    load_stage(0, 0);

    uint32_t qf[8][4];
    float acc_o[8][2][4];
#pragma unroll
    for (int gd = 0; gd < 8; gd++)
#pragma unroll
        for (int p = 0; p < 2; p++)
#pragma unroll
            for (int c = 0; c < 4; c++) acc_o[gd][p][c] = 0.f;
    float m0 = MASKV, m1 = MASKV, l0 = 0.f, l1 = 0.f;

    const int ktmax = 2 * qb + 1;
    const int q_row0 = qb * 128 + wq0 + gr;

    for (int kt = 0; kt <= ktmax; kt++) {
        const int buf = kt & 1;
        if (kt < ktmax) {
            load_stage(kt + 1, buf ^ 1);
            asm volatile("cp.async.wait_group 1;" ::: "memory");
        } else {
            asm volatile("cp.async.wait_group 0;" ::: "memory");
        }
        __syncthreads();

        if (kt == 0) {
#pragma unroll
            for (int dc = 0; dc < 8; dc++) {
                uint32_t off = sb + SM_Q + (uint32_t)((wq0 + lr) * QSTR + dc * 16 + lc) * 2;
                ldsm_x4(off, qf[dc][0], qf[dc][1], qf[dc][2], qf[dc][3]);
            }
        }

        const uint32_t kb_ = sb + SM_K + buf * 17408;
        const uint32_t vb_ = sb + SM_VT + buf * 18432;

        float s[4][2][4];
#pragma unroll
        for (int g = 0; g < 4; g++)
#pragma unroll
            for (int p = 0; p < 2; p++)
#pragma unroll
                for (int c = 0; c < 4; c++) s[g][p][c] = 0.f;
#pragma unroll
        for (int dc = 0; dc < 8; dc++)
#pragma unroll
            for (int g = 0; g < 4; g++) {
                uint32_t kbt[4];
                ldsm_x4(kb_ + (uint32_t)((g * 16 + lr) * QSTR + dc * 16 + lc) * 2,
                        kbt[0], kbt[1], kbt[2], kbt[3]);
                mma_f16(s[g][0], qf[dc], kbt[0], kbt[2]);
                mma_f16(s[g][1], qf[dc], kbt[1], kbt[3]);
            }

        if (kt >= 2 * qb) {
#pragma unroll
            for (int g = 0; g < 4; g++)
#pragma unroll
                for (int p = 0; p < 2; p++) {
                    int key = kt * 64 + g * 16 + p * 8 + gc;
                    if (key > q_row0)     s[g][p][0] = MASKV;
                    if (key + 1 > q_row0) s[g][p][1] = MASKV;
                    if (key > q_row0 + 8)     s[g][p][2] = MASKV;
                    if (key + 1 > q_row0 + 8) s[g][p][3] = MASKV;
                }
        }

        float t0 = MASKV, t1 = MASKV;
#pragma unroll
        for (int g = 0; g < 4; g++)
#pragma unroll
            for (int p = 0; p < 2; p++) {
                t0 = fmaxf(t0, fmaxf(s[g][p][0], s[g][p][1]));
                t1 = fmaxf(t1, fmaxf(s[g][p][2], s[g][p][3]));
            }
        t0 = fmaxf(t0, __shfl_xor_sync(0xffffffffu, t0, 1));
        t0 = fmaxf(t0, __shfl_xor_sync(0xffffffffu, t0, 2));
        t1 = fmaxf(t1, __shfl_xor_sync(0xffffffffu, t1, 1));
        t1 = fmaxf(t1, __shfl_xor_sync(0xffffffffu, t1, 2));
        float mn0 = fmaxf(m0, t0), mn1 = fmaxf(m1, t1);
        float a0 = ex2f((m0 - mn0) * CEXP), a1 = ex2f((m1 - mn1) * CEXP);
        m0 = mn0; m1 = mn1;

        uint32_t pah[4][4];
        float sum0 = 0.f, sum1 = 0.f;
#pragma unroll
        for (int g = 0; g < 4; g++)
#pragma unroll
            for (int p = 0; p < 2; p++) {
                float p0 = ex2f((s[g][p][0] - mn0) * CEXP);
                float p1 = ex2f((s[g][p][1] - mn0) * CEXP);
                float p2 = ex2f((s[g][p][2] - mn1) * CEXP);
                float p3 = ex2f((s[g][p][3] - mn1) * CEXP);
                sum0 += p0 + p1; sum1 += p2 + p3;
                pah[g][2 * p]     = pack2h(p0, p1);
                pah[g][2 * p + 1] = pack2h(p2, p3);
            }
        sum0 += __shfl_xor_sync(0xffffffffu, sum0, 1);
        sum0 += __shfl_xor_sync(0xffffffffu, sum0, 2);
        sum1 += __shfl_xor_sync(0xffffffffu, sum1, 1);
        sum1 += __shfl_xor_sync(0xffffffffu, sum1, 2);
        l0 = l0 * a0 + sum0;
        l1 = l1 * a1 + sum1;

#pragma unroll
        for (int gd = 0; gd < 8; gd++)
#pragma unroll
            for (int p = 0; p < 2; p++) {
                acc_o[gd][p][0] *= a0; acc_o[gd][p][1] *= a0;
                acc_o[gd][p][2] *= a1; acc_o[gd][p][3] *= a1;
            }

        // ---- O += P V  (fp16) ----
#pragma unroll
        for (int kc = 0; kc < 4; kc++)
#pragma unroll
            for (int gd = 0; gd < 8; gd++) {
                uint32_t off = (uint32_t)((gd * 16 + lr) * VTSTR + kc * 16 + lc) * 2;
                uint32_t bvh[4];
                ldsm_x4(vb_ + off, bvh[0], bvh[1], bvh[2], bvh[3]);
                mma_f16(acc_o[gd][0], pah[kc], bvh[0], bvh[2]);
                mma_f16(acc_o[gd][1], pah[kc], bvh[1], bvh[3]);
            }
        __syncthreads();
    }

    const float i0 = 1.f / l0, i1 = 1.f / l1;
    const size_t tok0 = (size_t)b * SEQ + qb * 128 + wq0 + gr;
#pragma unroll
    for (int gd = 0; gd < 8; gd++)
#pragma unroll
        for (int p = 0; p < 2; p++) {
            int col = h * HD + gd * 16 + p * 8 + gc;
            size_t o0 = tok0 * DMODEL + col, o1 = (tok0 + 8) * DMODEL + col;
            *(uint32_t*)&ath[o0] = pack2h(acc_o[gd][p][0] * i0, acc_o[gd][p][1] * i0);
            *(uint32_t*)&ath[o1] = pack2h(acc_o[gd][p][2] * i1, acc_o[gd][p][3] * i1);
        }
}

// ---------------------------------------------------------------------------
extern "C" void kernel_launch(void* const* d_in, const int* in_sizes, int n_in,
                              void* d_out, int out_size)
{
    const float* x    = (const float*)d_in[0];
    const float* Wqkv = (const float*)d_in[1];
    const float* Wo   = (const float*)d_in[2];
    float* out = (float*)d_out;

    void* p;
    cudaGetSymbolAddress(&p, g_xh);    ushort* xh  = (ushort*)p;
    cudaGetSymbolAddress(&p, g_wqkvh); ushort* wqh = (ushort*)p;
    cudaGetSymbolAddress(&p, g_woh);   ushort* woh = (ushort*)p;
    cudaGetSymbolAddress(&p, g_qkvh);  ushort* qvh = (ushort*)p;
    cudaGetSymbolAddress(&p, g_vth);   ushort* vth = (ushort*)p;
    cudaGetSymbolAddress(&p, g_ath);   ushort* ath = (ushort*)p;

    cudaFuncSetAttribute(gemm_f16<0>, cudaFuncAttributeMaxDynamicSharedMemorySize,
                         GEMM_SMEM);
    cudaFuncSetAttribute(gemm_f16<1>, cudaFuncAttributeMaxDynamicSharedMemorySize,
                         GEMM_SMEM);
    cudaFuncSetAttribute(attn_mma, cudaFuncAttributeMaxDynamicSharedMemorySize,
                         ATTN_SMEM_BYTES);

    // 0) convert inputs to fp16
    cvt_kernel<<<(NR * DMODEL / 4 + 255) / 256, 256>>>(x, xh, NR * DMODEL / 4);
    cvt_kernel<<<(TDMODEL * DMODEL / 4 + 255) / 256, 256>>>(Wqkv, wqh,
                                                            TDMODEL * DMODEL / 4);
    cvt_kernel<<<(DMODEL * DMODEL / 4 + 255) / 256, 256>>>(Wo, woh,
                                                           DMODEL * DMODEL / 4);

    // 1) fused qkv projection (fp16 1-pass, uniform epilogue)
    gemm_f16<1><<<dim3(TDMODEL / 128, NR / 128), 256, GEMM_SMEM>>>(
        xh, wqh, nullptr, qvh, TDMODEL, DMODEL);

    // 2) transpose V panel
    vtrans_kernel<<<dim3(SEQ / 32, HD / 32, NB * NH), dim3(32, 8)>>>(qvh, vth);

    // 3) attention -> fp16
    attn_mma<<<dim3(16, NH, NB), 256, ATTN_SMEM_BYTES>>>(qvh, vth, ath);

    // 4) out = att @ Wo^T (fp32 out)
    gemm_f16<0><<<dim3(DMODEL / 128, NR / 128), 256, GEMM_SMEM>>>(
        ath, woh, out, nullptr, DMODEL, DMODEL);
}

// round 15
// speedup vs baseline: 2.3387x; 1.0546x over previous
#include <cuda_runtime.h>
#include <cuda_bf16.h>
#include <math.h>
#include <stdint.h>

#define DMODEL 2048
#define TDMODEL 6144
#define NR 4096      // B*S rows
#define NH 16
#define HD 128
#define SEQ 2048
#define NB 2

// ---------------------------------------------------------------------------
// Scratch (no allocations allowed) — fp16 bit-planes
// ---------------------------------------------------------------------------
__device__ ushort g_xh[(size_t)NR * DMODEL];
__device__ ushort g_wqkvh[(size_t)TDMODEL * DMODEL];
__device__ ushort g_woh[(size_t)DMODEL * DMODEL];
__device__ ushort g_qkvh[(size_t)NR * TDMODEL];       // q,k,v all fp16
__device__ ushort g_vth[(size_t)NB * NH * HD * SEQ];  // [b][h][d][tok]
__device__ ushort g_ath[(size_t)NR * DMODEL];

// ---------------------------------------------------------------------------
// PTX helpers (sm_80+ portable)
// ---------------------------------------------------------------------------
__device__ __forceinline__ uint32_t smem_u32(const void* p) {
    uint32_t a;
    asm("{ .reg .u64 t; cvta.to.shared.u64 t, %1; cvt.u32.u64 %0, t; }" : "=r"(a) : "l"(p));
    return a;
}
__device__ __forceinline__ void cp16(uint32_t dst, const void* src) {
    asm volatile("cp.async.cg.shared.global [%0], [%1], 16;" :: "r"(dst), "l"(src));
}
__device__ __forceinline__ void ldsm_x4(uint32_t addr, uint32_t& r0, uint32_t& r1,
                                        uint32_t& r2, uint32_t& r3) {
    asm volatile("ldmatrix.sync.aligned.m8n8.x4.shared.b16 {%0,%1,%2,%3}, [%4];"
                 : "=r"(r0), "=r"(r1), "=r"(r2), "=r"(r3) : "r"(addr));
}
__device__ __forceinline__ void mma_f16(float* d, const uint32_t* a,
                                        uint32_t b0, uint32_t b1) {
    asm volatile(
        "mma.sync.aligned.m16n8k16.row.col.f32.f16.f16.f32 "
        "{%0,%1,%2,%3}, {%4,%5,%6,%7}, {%8,%9}, {%0,%1,%2,%3};"
        : "+f"(d[0]), "+f"(d[1]), "+f"(d[2]), "+f"(d[3])
        : "r"(a[0]), "r"(a[1]), "r"(a[2]), "r"(a[3]), "r"(b0), "r"(b1));
}
__device__ __forceinline__ float ex2f(float x) {
    float y; asm("ex2.approx.f32 %0, %1;" : "=f"(y) : "f"(x)); return y;
}
// pack {lo, hi} fp32 -> f16x2 (lo in bits [0:16))
__device__ __forceinline__ uint32_t pack2h(float lo, float hi) {
    uint32_t r;
    asm("cvt.rn.f16x2.f32 %0, %1, %2;" : "=r"(r) : "f"(hi), "f"(lo));
    return r;
}

// ---------------------------------------------------------------------------
// Convert fp32 -> fp16
// ---------------------------------------------------------------------------
__global__ void cvt_kernel(const float* __restrict__ s, ushort* __restrict__ h, int n4)
{
    int i = blockIdx.x * blockDim.x + threadIdx.x;
    if (i >= n4) return;
    float4 v = ((const float4*)s)[i];
    uint2 uh;
    uh.x = pack2h(v.x, v.y);
    uh.y = pack2h(v.z, v.w);
    ((uint2*)h)[i] = uh;
}

// ---------------------------------------------------------------------------
// V transpose (fp16 bits): qkv[tok][4096 + h*128 + d] -> vt[(b,h)][d][tok]
// ---------------------------------------------------------------------------
__global__ void vtrans_kernel(const ushort* __restrict__ qh, ushort* __restrict__ vh)
{
    __shared__ ushort t0[32][33];
    const int bh = blockIdx.z, b = bh >> 4, h = bh & 15;
    const int tok0 = blockIdx.x * 32, d0 = blockIdx.y * 32;
    const int tx = threadIdx.x, ty = threadIdx.y;
    const size_t sbase = ((size_t)(b * SEQ + tok0)) * TDMODEL + 2 * DMODEL + h * HD + d0;
#pragma unroll
    for (int i = 0; i < 4; i++) {
        int r = ty + i * 8;
        t0[r][tx] = qh[sbase + (size_t)r * TDMODEL + tx];
    }
    __syncthreads();
    const size_t dbase = ((size_t)(bh * HD + d0)) * SEQ + tok0;
#pragma unroll
    for (int i = 0; i < 4; i++) {
        int r = ty + i * 8;
        vh[dbase + (size_t)r * SEQ + tx] = t0[tx][r];
    }
}

// ---------------------------------------------------------------------------
// mma.sync NT GEMM, single-pass fp16, fp32 accumulate.
// EMIT: 0 = fp32 -> C, 1 = fp16 -> Ch.
// 128x128 tile, BK=64 stages (128 MMAs per barrier), 8 warps, warp 64x32,
// 3-stage cp.async ring. smem rows are 128 B, swizzle chunk^(row&7).
// ---------------------------------------------------------------------------
#define TS 16384u                        // 128 rows x 128 B per operand stage
#define NSTG 3
#define GEMM_SMEM (2 * NSTG * TS + 1024) // 99328

template<int EMIT>
__global__ __launch_bounds__(256, 2)
void gemm_f16(const ushort* __restrict__ A, const ushort* __restrict__ B,
              float* __restrict__ C, ushort* __restrict__ Ch, int ldc, int K)
{
    extern __shared__ char smem[];
    const uint32_t sb = (smem_u32(smem) + 1023u) & ~1023u;
    const uint32_t sA = sb;
    const uint32_t sB = sb + NSTG * TS;

    const int tid = threadIdx.x, lane = tid & 31, wid = tid >> 5;
    const int bm = blockIdx.y * 128, bn = blockIdx.x * 128;
    const int m0 = (wid & 1) * 64, n0 = (wid >> 1) * 32;

    const char* gA = (const char*)(A + (size_t)bm * K);
    const char* gB = (const char*)(B + (size_t)bn * K);

    float acc[4][4][4];
#pragma unroll
    for (int i = 0; i < 4; i++)
#pragma unroll
        for (int j = 0; j < 4; j++)
#pragma unroll
            for (int c = 0; c < 4; c++) acc[i][j][c] = 0.f;

    // ---- cp.async offsets: 1024 chunks per operand, 4 per thread ----
    uint32_t cpRel[4], goRow[4];
#pragma unroll
    for (int t = 0; t < 4; t++) {
        int c = tid + t * 256;
        int row = c >> 3, ch = c & 7;
        cpRel[t] = (uint32_t)(row * 128 + (ch ^ (row & 7)) * 16);
        goRow[t] = (uint32_t)(row * K * 2 + ch * 16);
    }

    // ---- ldsm addresses for ks 0,1 (ks 2,3 = ^64) ----
    const int lr = lane & 15;
    const uint32_t hc = (uint32_t)(lane >> 4);      // 0 or 1
    uint32_t aAddr[4][2], bAddr[2][2];
#pragma unroll
    for (int mt = 0; mt < 4; mt++) {
        uint32_t row = (uint32_t)(m0 + mt * 16 + lr);
#pragma unroll
        for (int ks = 0; ks < 2; ks++)
            aAddr[mt][ks] = sA + row * 128 + ((((uint32_t)ks * 2 + hc) ^ (row & 7u)) << 4);
    }
#pragma unroll
    for (int g = 0; g < 2; g++) {
        uint32_t row = (uint32_t)(n0 + g * 16 + lr);
#pragma unroll
        for (int ks = 0; ks < 2; ks++)
            bAddr[g][ks] = sB + row * 128 + ((((uint32_t)ks * 2 + hc) ^ (row & 7u)) << 4);
    }

    auto load_stage = [&](int kb, uint32_t bufo) {
        const uint32_t gofs = (uint32_t)kb * 128;
#pragma unroll
        for (int t = 0; t < 4; t++) {
            uint32_t so = cpRel[t] + bufo;
            uint32_t go = goRow[t] + gofs;
            cp16(sA + so, gA + go);
            cp16(sB + so, gB + go);
        }
        asm volatile("cp.async.commit_group;" ::: "memory");
    };

    const int nk = K / 64;
    load_stage(0, 0);
    load_stage(1, TS);

    for (int kb0 = 0; kb0 < nk; kb0 += NSTG) {
#pragma unroll
        for (int u = 0; u < NSTG; u++) {
            const int kb = kb0 + u;
            if (kb >= nk) break;
            asm volatile("cp.async.wait_group %0;" :: "n"(NSTG - 2) : "memory");
            __syncthreads();
            {
                int nkb = kb + NSTG - 1;
                const uint32_t nbufo = (uint32_t)((u + NSTG - 1) % NSTG) * TS;
                if (nkb < nk) load_stage(nkb, nbufo);
                else asm volatile("cp.async.commit_group;" ::: "memory");
            }
            const uint32_t bufo = (uint32_t)u * TS;

#pragma unroll
            for (int ks = 0; ks < 4; ks++) {
                const int ksl = ks & 1;
                const uint32_t x = (ks & 2) ? 64u : 0u;    // ks 2,3: flip bit 6
                uint32_t ah[4][4], bh[2][4];
#pragma unroll
                for (int mt = 0; mt < 4; mt++)
                    ldsm_x4((aAddr[mt][ksl] ^ x) + bufo,
                            ah[mt][0], ah[mt][1], ah[mt][2], ah[mt][3]);
#pragma unroll
                for (int g = 0; g < 2; g++)
                    ldsm_x4((bAddr[g][ksl] ^ x) + bufo,
                            bh[g][0], bh[g][1], bh[g][2], bh[g][3]);
#pragma unroll
                for (int mt = 0; mt < 4; mt++)
#pragma unroll
                    for (int nt = 0; nt < 4; nt++) {
                        const int g = nt >> 1, p = nt & 1;
                        mma_f16(acc[mt][nt], ah[mt], bh[g][p], bh[g][p + 2]);
                    }
            }
        }
    }

    const int gr = lane >> 2, gc = (lane & 3) * 2;
#pragma unroll
    for (int mt = 0; mt < 4; mt++)
#pragma unroll
        for (int nt = 0; nt < 4; nt++) {
            int r = bm + m0 + mt * 16 + gr;
            int cix = bn + n0 + nt * 8 + gc;
            if (EMIT == 0) {
                *(float2*)&C[(size_t)r * ldc + cix] =
                    make_float2(acc[mt][nt][0], acc[mt][nt][1]);
                *(float2*)&C[(size_t)(r + 8) * ldc + cix] =
                    make_float2(acc[mt][nt][2], acc[mt][nt][3]);
            } else {
                *(uint32_t*)&Ch[(size_t)r * ldc + cix] =
                    pack2h(acc[mt][nt][0], acc[mt][nt][1]);
                *(uint32_t*)&Ch[(size_t)(r + 8) * ldc + cix] =
                    pack2h(acc[mt][nt][2], acc[mt][nt][3]);
            }
        }
}

// ---------------------------------------------------------------------------
// Tensor-core causal flash attention, all-fp16 operands, fp32 accum/softmax.
// (unchanged from R14)
// ---------------------------------------------------------------------------
#define QSTR 136
#define VTSTR 72
#define SM_Q 0
#define SM_K 34816
#define SM_VT 69632
#define ATTN_SMEM_BYTES 106496
#define CEXP 0.12751744f                 // log2(e)/sqrt(128)
#define MASKV (-1e30f)

__global__ __launch_bounds__(256, 1)
void attn_mma(const ushort* __restrict__ qkvh,
              const ushort* __restrict__ vth,
              ushort* __restrict__ ath)
{
    extern __shared__ char smem[];
    const uint32_t sb = smem_u32(smem);

    const int tid = threadIdx.x, lane = tid & 31, wid = tid >> 5;
    const int qb = 15 - blockIdx.x;
    const int h = blockIdx.y, b = blockIdx.z;
    const int wq0 = wid * 16;
    const int lr = lane & 15, lc = (lane >> 4) * 8;
    const int gr = lane >> 2, gc = (lane & 3) * 2;

    const char* gQ = (const char*)qkvh + ((size_t)(b * SEQ + qb * 128)) * (TDMODEL * 2)
                     + h * 256;
    const char* gK = (const char*)qkvh + ((size_t)(b * SEQ)) * (TDMODEL * 2)
                     + DMODEL * 2 + h * 256;
    const char* gVh = (const char*)vth + ((size_t)((b * NH + h) * HD)) * (SEQ * 2);

    {
#pragma unroll
        for (int i = 0; i < 8; i++) {
            int c = tid + i * 256;
            int row = c >> 4, coff = (c & 15) * 16;
            cp16(sb + SM_Q + row * (QSTR * 2) + coff, gQ + (size_t)row * 12288 + coff);
        }
        asm volatile("cp.async.commit_group;" ::: "memory");
    }
    auto load_stage = [&](int kt, int buf) {
        const uint32_t kb_ = sb + SM_K + buf * 17408;
        const uint32_t vb_ = sb + SM_VT + buf * 18432;
#pragma unroll
        for (int i = 0; i < 4; i++) {
            int c = tid + i * 256;
            int row = c >> 4, coff = (c & 15) * 16;
            cp16(kb_ + row * (QSTR * 2) + coff,
                 gK + (size_t)(kt * 64 + row) * 12288 + coff);
        }
#pragma unroll
        for (int i = 0; i < 4; i++) {
            int c = tid + i * 256;
            int row = c >> 3, coff = (c & 7) * 16;
            size_t go = (size_t)row * (SEQ * 2) + (size_t)kt * 128 + coff;
            cp16(vb_ + row * (VTSTR * 2) + coff, gVh + go);
        }
        asm volatile("cp.async.commit_group;" ::: "memory");
    };
    load_stage(0, 0);

    uint32_t qf[8][4];
    float acc_o[8][2][4];
#pragma unroll
    for (int gd = 0; gd < 8; gd++)
#pragma unroll
        for (int p = 0; p < 2; p++)
#pragma unroll
            for (int c = 0; c < 4; c++) acc_o[gd][p][c] = 0.f;
    float m0 = MASKV, m1 = MASKV, l0 = 0.f, l1 = 0.f;

    const int ktmax = 2 * qb + 1;
    const int q_row0 = qb * 128 + wq0 + gr;

    for (int kt = 0; kt <= ktmax; kt++) {
        const int buf = kt & 1;
        if (kt < ktmax) {
            load_stage(kt + 1, buf ^ 1);
            asm volatile("cp.async.wait_group 1;" ::: "memory");
        } else {
            asm volatile("cp.async.wait_group 0;" ::: "memory");
        }
        __syncthreads();

        if (kt == 0) {
#pragma unroll
            for (int dc = 0; dc < 8; dc++) {
                uint32_t off = sb + SM_Q + (uint32_t)((wq0 + lr) * QSTR + dc * 16 + lc) * 2;
                ldsm_x4(off, qf[dc][0], qf[dc][1], qf[dc][2], qf[dc][3]);
            }
        }

        const uint32_t kb_ = sb + SM_K + buf * 17408;
        const uint32_t vb_ = sb + SM_VT + buf * 18432;

        float s[4][2][4];
#pragma unroll
        for (int g = 0; g < 4; g++)
#pragma unroll
            for (int p = 0; p < 2; p++)
#pragma unroll
                for (int c = 0; c < 4; c++) s[g][p][c] = 0.f;
#pragma unroll
        for (int dc = 0; dc < 8; dc++)
#pragma unroll
            for (int g = 0; g < 4; g++) {
                uint32_t kbt[4];
                ldsm_x4(kb_ + (uint32_t)((g * 16 + lr) * QSTR + dc * 16 + lc) * 2,
                        kbt[0], kbt[1], kbt[2], kbt[3]);
                mma_f16(s[g][0], qf[dc], kbt[0], kbt[2]);
                mma_f16(s[g][1], qf[dc], kbt[1], kbt[3]);
            }

        if (kt >= 2 * qb) {
#pragma unroll
            for (int g = 0; g < 4; g++)
#pragma unroll
                for (int p = 0; p < 2; p++) {
                    int key = kt * 64 + g * 16 + p * 8 + gc;
                    if (key > q_row0)     s[g][p][0] = MASKV;
                    if (key + 1 > q_row0) s[g][p][1] = MASKV;
                    if (key > q_row0 + 8)     s[g][p][2] = MASKV;
                    if (key + 1 > q_row0 + 8) s[g][p][3] = MASKV;
                }
        }

        float t0 = MASKV, t1 = MASKV;
#pragma unroll
        for (int g = 0; g < 4; g++)
#pragma unroll
            for (int p = 0; p < 2; p++) {
                t0 = fmaxf(t0, fmaxf(s[g][p][0], s[g][p][1]));
                t1 = fmaxf(t1, fmaxf(s[g][p][2], s[g][p][3]));
            }
        t0 = fmaxf(t0, __shfl_xor_sync(0xffffffffu, t0, 1));
        t0 = fmaxf(t0, __shfl_xor_sync(0xffffffffu, t0, 2));
        t1 = fmaxf(t1, __shfl_xor_sync(0xffffffffu, t1, 1));
        t1 = fmaxf(t1, __shfl_xor_sync(0xffffffffu, t1, 2));
        float mn0 = fmaxf(m0, t0), mn1 = fmaxf(m1, t1);
        float a0 = ex2f((m0 - mn0) * CEXP), a1 = ex2f((m1 - mn1) * CEXP);
        m0 = mn0; m1 = mn1;

        uint32_t pah[4][4];
        float sum0 = 0.f, sum1 = 0.f;
#pragma unroll
        for (int g = 0; g < 4; g++)
#pragma unroll
            for (int p = 0; p < 2; p++) {
                float p0 = ex2f((s[g][p][0] - mn0) * CEXP);
                float p1 = ex2f((s[g][p][1] - mn0) * CEXP);
                float p2 = ex2f((s[g][p][2] - mn1) * CEXP);
                float p3 = ex2f((s[g][p][3] - mn1) * CEXP);
                sum0 += p0 + p1; sum1 += p2 + p3;
                pah[g][2 * p]     = pack2h(p0, p1);
                pah[g][2 * p + 1] = pack2h(p2, p3);
            }
        sum0 += __shfl_xor_sync(0xffffffffu, sum0, 1);
        sum0 += __shfl_xor_sync(0xffffffffu, sum0, 2);
        sum1 += __shfl_xor_sync(0xffffffffu, sum1, 1);
        sum1 += __shfl_xor_sync(0xffffffffu, sum1, 2);
        l0 = l0 * a0 + sum0;
        l1 = l1 * a1 + sum1;

#pragma unroll
        for (int gd = 0; gd < 8; gd++)
#pragma unroll
            for (int p = 0; p < 2; p++) {
                acc_o[gd][p][0] *= a0; acc_o[gd][p][1] *= a0;
                acc_o[gd][p][2] *= a1; acc_o[gd][p][3] *= a1;
            }

#pragma unroll
        for (int kc = 0; kc < 4; kc++)
#pragma unroll
            for (int gd = 0; gd < 8; gd++) {
                uint32_t off = (uint32_t)((gd * 16 + lr) * VTSTR + kc * 16 + lc) * 2;
                uint32_t bvh[4];
                ldsm_x4(vb_ + off, bvh[0], bvh[1], bvh[2], bvh[3]);
                mma_f16(acc_o[gd][0], pah[kc], bvh[0], bvh[2]);
                mma_f16(acc_o[gd][1], pah[kc], bvh[1], bvh[3]);
            }
        __syncthreads();
    }

    const float i0 = 1.f / l0, i1 = 1.f / l1;
    const size_t tok0 = (size_t)b * SEQ + qb * 128 + wq0 + gr;
#pragma unroll
    for (int gd = 0; gd < 8; gd++)
#pragma unroll
        for (int p = 0; p < 2; p++) {
            int col = h * HD + gd * 16 + p * 8 + gc;
            size_t o0 = tok0 * DMODEL + col, o1 = (tok0 + 8) * DMODEL + col;
            *(uint32_t*)&ath[o0] = pack2h(acc_o[gd][p][0] * i0, acc_o[gd][p][1] * i0);
            *(uint32_t*)&ath[o1] = pack2h(acc_o[gd][p][2] * i1, acc_o[gd][p][3] * i1);
        }
}

// ---------------------------------------------------------------------------
extern "C" void kernel_launch(void* const* d_in, const int* in_sizes, int n_in,
                              void* d_out, int out_size)
{
    const float* x    = (const float*)d_in[0];
    const float* Wqkv = (const float*)d_in[1];
    const float* Wo   = (const float*)d_in[2];
    float* out = (float*)d_out;

    void* p;
    cudaGetSymbolAddress(&p, g_xh);    ushort* xh  = (ushort*)p;
    cudaGetSymbolAddress(&p, g_wqkvh); ushort* wqh = (ushort*)p;
    cudaGetSymbolAddress(&p, g_woh);   ushort* woh = (ushort*)p;
    cudaGetSymbolAddress(&p, g_qkvh);  ushort* qvh = (ushort*)p;
    cudaGetSymbolAddress(&p, g_vth);   ushort* vth = (ushort*)p;
    cudaGetSymbolAddress(&p, g_ath);   ushort* ath = (ushort*)p;

    cudaFuncSetAttribute(gemm_f16<0>, cudaFuncAttributeMaxDynamicSharedMemorySize,
                         GEMM_SMEM);
    cudaFuncSetAttribute(gemm_f16<1>, cudaFuncAttributeMaxDynamicSharedMemorySize,
                         GEMM_SMEM);
    cudaFuncSetAttribute(attn_mma, cudaFuncAttributeMaxDynamicSharedMemorySize,
                         ATTN_SMEM_BYTES);

    // 0) convert inputs to fp16
    cvt_kernel<<<(NR * DMODEL / 4 + 255) / 256, 256>>>(x, xh, NR * DMODEL / 4);
    cvt_kernel<<<(TDMODEL * DMODEL / 4 + 255) / 256, 256>>>(Wqkv, wqh,
                                                            TDMODEL * DMODEL / 4);
    cvt_kernel<<<(DMODEL * DMODEL / 4 + 255) / 256, 256>>>(Wo, woh,
                                                           DMODEL * DMODEL / 4);

    // 1) fused qkv projection (fp16 1-pass)
    gemm_f16<1><<<dim3(TDMODEL / 128, NR / 128), 256, GEMM_SMEM>>>(
        xh, wqh, nullptr, qvh, TDMODEL, DMODEL);

    // 2) transpose V panel
    vtrans_kernel<<<dim3(SEQ / 32, HD / 32, NB * NH), dim3(32, 8)>>>(qvh, vth);

    // 3) attention -> fp16
    attn_mma<<<dim3(16, NH, NB), 256, ATTN_SMEM_BYTES>>>(qvh, vth, ath);

    // 4) out = att @ Wo^T (fp32 out)
    gemm_f16<0><<<dim3(DMODEL / 128, NR / 128), 256, GEMM_SMEM>>>(
        ath, woh, out, nullptr, DMODEL, DMODEL);
}

// round 16
// speedup vs baseline: 2.3451x; 1.0027x over previous
#include <cuda_runtime.h>
#include <cuda_bf16.h>
#include <math.h>
#include <stdint.h>

#define DMODEL 2048
#define TDMODEL 6144
#define NR 4096      // B*S rows
#define NH 16
#define HD 128
#define SEQ 2048
#define NB 2

// ---------------------------------------------------------------------------
// Scratch (no allocations allowed) — fp16 bit-planes
// ---------------------------------------------------------------------------
__device__ ushort g_xh[(size_t)NR * DMODEL];
__device__ ushort g_wqkvh[(size_t)TDMODEL * DMODEL];
__device__ ushort g_woh[(size_t)DMODEL * DMODEL];
__device__ ushort g_qkvh[(size_t)NR * TDMODEL];       // q,k,v all fp16
__device__ ushort g_vth[(size_t)NB * NH * HD * SEQ];  // [b][h][d][tok]
__device__ ushort g_ath[(size_t)NR * DMODEL];

// ---------------------------------------------------------------------------
// PTX helpers (sm_80+ portable)
// ---------------------------------------------------------------------------
__device__ __forceinline__ uint32_t smem_u32(const void* p) {
    uint32_t a;
    asm("{ .reg .u64 t; cvta.to.shared.u64 t, %1; cvt.u32.u64 %0, t; }" : "=r"(a) : "l"(p));
    return a;
}
__device__ __forceinline__ void cp16(uint32_t dst, const void* src) {
    asm volatile("cp.async.cg.shared.global [%0], [%1], 16;" :: "r"(dst), "l"(src));
}
__device__ __forceinline__ void ldsm_x4(uint32_t addr, uint32_t& r0, uint32_t& r1,
                                        uint32_t& r2, uint32_t& r3) {
    asm volatile("ldmatrix.sync.aligned.m8n8.x4.shared.b16 {%0,%1,%2,%3}, [%4];"
                 : "=r"(r0), "=r"(r1), "=r"(r2), "=r"(r3) : "r"(addr));
}
__device__ __forceinline__ void mma_f16(float* d, const uint32_t* a,
                                        uint32_t b0, uint32_t b1) {
    asm volatile(
        "mma.sync.aligned.m16n8k16.row.col.f32.f16.f16.f32 "
        "{%0,%1,%2,%3}, {%4,%5,%6,%7}, {%8,%9}, {%0,%1,%2,%3};"
        : "+f"(d[0]), "+f"(d[1]), "+f"(d[2]), "+f"(d[3])
        : "r"(a[0]), "r"(a[1]), "r"(a[2]), "r"(a[3]), "r"(b0), "r"(b1));
}
__device__ __forceinline__ float ex2f(float x) {
    float y; asm("ex2.approx.f32 %0, %1;" : "=f"(y) : "f"(x)); return y;
}
// pack {lo, hi} fp32 -> f16x2 (lo in bits [0:16))
__device__ __forceinline__ uint32_t pack2h(float lo, float hi) {
    uint32_t r;
    asm("cvt.rn.f16x2.f32 %0, %1, %2;" : "=r"(r) : "f"(hi), "f"(lo));
    return r;
}

// ---------------------------------------------------------------------------
// Convert fp32 -> fp16
// ---------------------------------------------------------------------------
__global__ void cvt_kernel(const float* __restrict__ s, ushort* __restrict__ h, int n4)
{
    int i = blockIdx.x * blockDim.x + threadIdx.x;
    if (i >= n4) return;
    float4 v = ((const float4*)s)[i];
    uint2 uh;
    uh.x = pack2h(v.x, v.y);
    uh.y = pack2h(v.z, v.w);
    ((uint2*)h)[i] = uh;
}

// ---------------------------------------------------------------------------
// V transpose (fp16 bits): qkv[tok][4096 + h*128 + d] -> vt[(b,h)][d][tok]
// ---------------------------------------------------------------------------
__global__ void vtrans_kernel(const ushort* __restrict__ qh, ushort* __restrict__ vh)
{
    __shared__ ushort t0[32][33];
    const int bh = blockIdx.z, b = bh >> 4, h = bh & 15;
    const int tok0 = blockIdx.x * 32, d0 = blockIdx.y * 32;
    const int tx = threadIdx.x, ty = threadIdx.y;
    const size_t sbase = ((size_t)(b * SEQ + tok0)) * TDMODEL + 2 * DMODEL + h * HD + d0;
#pragma unroll
    for (int i = 0; i < 4; i++) {
        int r = ty + i * 8;
        t0[r][tx] = qh[sbase + (size_t)r * TDMODEL + tx];
    }
    __syncthreads();
    const size_t dbase = ((size_t)(bh * HD + d0)) * SEQ + tok0;
#pragma unroll
    for (int i = 0; i < 4; i++) {
        int r = ty + i * 8;
        vh[dbase + (size_t)r * SEQ + tx] = t0[tx][r];
    }
}

// ---------------------------------------------------------------------------
// mma.sync NT GEMM, single-pass fp16, fp32 accumulate.
// EMIT: 0 = fp32 -> C, 1 = fp16 -> Ch.
// CTA 128x128, 4 warps (128 threads), warp tile 64x64 (32 MMAs/ks),
// BK=64 stages, 3-stage cp.async ring. smem rows 128 B, swizzle chunk^(row&7).
// ---------------------------------------------------------------------------
#define TS 16384u                        // 128 rows x 128 B per operand stage
#define NSTG 3
#define GEMM_SMEM (2 * NSTG * TS + 1024) // 99328

template<int EMIT>
__global__ __launch_bounds__(128, 2)
void gemm_f16(const ushort* __restrict__ A, const ushort* __restrict__ B,
              float* __restrict__ C, ushort* __restrict__ Ch, int ldc, int K)
{
    extern __shared__ char smem[];
    const uint32_t sb = (smem_u32(smem) + 1023u) & ~1023u;
    const uint32_t sA = sb;
    const uint32_t sB = sb + NSTG * TS;

    const int tid = threadIdx.x, lane = tid & 31, wid = tid >> 5;
    const int bm = blockIdx.y * 128, bn = blockIdx.x * 128;
    const int m0 = (wid & 1) * 64, n0 = (wid >> 1) * 64;

    const char* gA = (const char*)(A + (size_t)bm * K);
    const char* gB = (const char*)(B + (size_t)bn * K);

    float acc[4][8][4];
#pragma unroll
    for (int i = 0; i < 4; i++)
#pragma unroll
        for (int j = 0; j < 8; j++)
#pragma unroll
            for (int c = 0; c < 4; c++) acc[i][j][c] = 0.f;

    // ---- cp.async offsets: 1024 chunks per operand, 8 per thread ----
    uint32_t cpRel[8], goRow[8];
#pragma unroll
    for (int t = 0; t < 8; t++) {
        int c = tid + t * 128;
        int row = c >> 3, ch = c & 7;
        cpRel[t] = (uint32_t)(row * 128 + (ch ^ (row & 7)) * 16);
        goRow[t] = (uint32_t)(row * K * 2 + ch * 16);
    }

    // ---- ldsm addresses for ks 0,1 (ks 2,3 = ^64) ----
    const int lr = lane & 15;
    const uint32_t hc = (uint32_t)(lane >> 4);      // 0 or 1
    uint32_t aAddr[4][2], bAddr[4][2];
#pragma unroll
    for (int mt = 0; mt < 4; mt++) {
        uint32_t row = (uint32_t)(m0 + mt * 16 + lr);
#pragma unroll
        for (int ks = 0; ks < 2; ks++)
            aAddr[mt][ks] = sA + row * 128 + ((((uint32_t)ks * 2 + hc) ^ (row & 7u)) << 4);
    }
#pragma unroll
    for (int g = 0; g < 4; g++) {
        uint32_t row = (uint32_t)(n0 + g * 16 + lr);
#pragma unroll
        for (int ks = 0; ks < 2; ks++)
            bAddr[g][ks] = sB + row * 128 + ((((uint32_t)ks * 2 + hc) ^ (row & 7u)) << 4);
    }

    auto load_stage = [&](int kb, uint32_t bufo) {
        const uint32_t gofs = (uint32_t)kb * 128;
#pragma unroll
        for (int t = 0; t < 8; t++) {
            uint32_t so = cpRel[t] + bufo;
            uint32_t go = goRow[t] + gofs;
            cp16(sA + so, gA + go);
            cp16(sB + so, gB + go);
        }
        asm volatile("cp.async.commit_group;" ::: "memory");
    };

    const int nk = K / 64;
    load_stage(0, 0);
    load_stage(1, TS);

    for (int kb0 = 0; kb0 < nk; kb0 += NSTG) {
#pragma unroll
        for (int u = 0; u < NSTG; u++) {
            const int kb = kb0 + u;
            if (kb >= nk) break;
            asm volatile("cp.async.wait_group %0;" :: "n"(NSTG - 2) : "memory");
            __syncthreads();
            {
                int nkb = kb + NSTG - 1;
                const uint32_t nbufo = (uint32_t)((u + NSTG - 1) % NSTG) * TS;
                if (nkb < nk) load_stage(nkb, nbufo);
                else asm volatile("cp.async.commit_group;" ::: "memory");
            }
            const uint32_t bufo = (uint32_t)u * TS;

#pragma unroll
            for (int ks = 0; ks < 4; ks++) {
                const int ksl = ks & 1;
                const uint32_t x = (ks & 2) ? 64u : 0u;    // ks 2,3: flip bit 6
                uint32_t ah[4][4], bh[4][4];
#pragma unroll
                for (int mt = 0; mt < 4; mt++)
                    ldsm_x4((aAddr[mt][ksl] ^ x) + bufo,
                            ah[mt][0], ah[mt][1], ah[mt][2], ah[mt][3]);
#pragma unroll
                for (int g = 0; g < 4; g++)
                    ldsm_x4((bAddr[g][ksl] ^ x) + bufo,
                            bh[g][0], bh[g][1], bh[g][2], bh[g][3]);
#pragma unroll
                for (int mt = 0; mt < 4; mt++)
#pragma unroll
                    for (int nt = 0; nt < 8; nt++) {
                        const int g = nt >> 1, p = nt & 1;
                        mma_f16(acc[mt][nt], ah[mt], bh[g][p], bh[g][p + 2]);
                    }
            }
        }
    }

    const int gr = lane >> 2, gc = (lane & 3) * 2;
#pragma unroll
    for (int mt = 0; mt < 4; mt++)
#pragma unroll
        for (int nt = 0; nt < 8; nt++) {
            int r = bm + m0 + mt * 16 + gr;
            int cix = bn + n0 + nt * 8 + gc;
            if (EMIT == 0) {
                *(float2*)&C[(size_t)r * ldc + cix] =
                    make_float2(acc[mt][nt][0], acc[mt][nt][1]);
                *(float2*)&C[(size_t)(r + 8) * ldc + cix] =
                    make_float2(acc[mt][nt][2], acc[mt][nt][3]);
            } else {
                *(uint32_t*)&Ch[(size_t)r * ldc + cix] =
                    pack2h(acc[mt][nt][0], acc[mt][nt][1]);
                *(uint32_t*)&Ch[(size_t)(r + 8) * ldc + cix] =
                    pack2h(acc[mt][nt][2], acc[mt][nt][3]);
            }
        }
}

// ---------------------------------------------------------------------------
// Tensor-core causal flash attention, all-fp16 operands, fp32 accum/softmax.
// (unchanged from R14)
// ---------------------------------------------------------------------------
#define QSTR 136
#define VTSTR 72
#define SM_Q 0
#define SM_K 34816
#define SM_VT 69632
#define ATTN_SMEM_BYTES 106496
#define CEXP 0.12751744f                 // log2(e)/sqrt(128)
#define MASKV (-1e30f)

__global__ __launch_bounds__(256, 1)
void attn_mma(const ushort* __restrict__ qkvh,
              const ushort* __restrict__ vth,
              ushort* __restrict__ ath)
{
    extern __shared__ char smem[];
    const uint32_t sb = smem_u32(smem);

    const int tid = threadIdx.x, lane = tid & 31, wid = tid >> 5;
    const int qb = 15 - blockIdx.x;
    const int h = blockIdx.y, b = blockIdx.z;
    const int wq0 = wid * 16;
    const int lr = lane & 15, lc = (lane >> 4) * 8;
    const int gr = lane >> 2, gc = (lane & 3) * 2;

    const char* gQ = (const char*)qkvh + ((size_t)(b * SEQ + qb * 128)) * (TDMODEL * 2)
                     + h * 256;
    const char* gK = (const char*)qkvh + ((size_t)(b * SEQ)) * (TDMODEL * 2)
                     + DMODEL * 2 + h * 256;
    const char* gVh = (const char*)vth + ((size_t)((b * NH + h) * HD)) * (SEQ * 2);

    {
#pragma unroll
        for (int i = 0; i < 8; i++) {
            int c = tid + i * 256;
            int row = c >> 4, coff = (c & 15) * 16;
            cp16(sb + SM_Q + row * (QSTR * 2) + coff, gQ + (size_t)row * 12288 + coff);
        }
        asm volatile("cp.async.commit_group;" ::: "memory");
    }
    auto load_stage = [&](int kt, int buf) {
        const uint32_t kb_ = sb + SM_K + buf * 17408;
        const uint32_t vb_ = sb + SM_VT + buf * 18432;
#pragma unroll
        for (int i = 0; i < 4; i++) {
            int c = tid + i * 256;
            int row = c >> 4, coff = (c & 15) * 16;
            cp16(kb_ + row * (QSTR * 2) + coff,
                 gK + (size_t)(kt * 64 + row) * 12288 + coff);
        }
#pragma unroll
        for (int i = 0; i < 4; i++) {
            int c = tid + i * 256;
            int row = c >> 3, coff = (c & 7) * 16;
            size_t go = (size_t)row * (SEQ * 2) + (size_t)kt * 128 + coff;
            cp16(vb_ + row * (VTSTR * 2) + coff, gVh + go);
        }
        asm volatile("cp.async.commit_group;" ::: "memory");
    };
    load_stage(0, 0);

    uint32_t qf[8][4];
    float acc_o[8][2][4];
#pragma unroll
    for (int gd = 0; gd < 8; gd++)
#pragma unroll
        for (int p = 0; p < 2; p++)
#pragma unroll
            for (int c = 0; c < 4; c++) acc_o[gd][p][c] = 0.f;
    float m0 = MASKV, m1 = MASKV, l0 = 0.f, l1 = 0.f;

    const int ktmax = 2 * qb + 1;
    const int q_row0 = qb * 128 + wq0 + gr;

    for (int kt = 0; kt <= ktmax; kt++) {
        const int buf = kt & 1;
        if (kt < ktmax) {
            load_stage(kt + 1, buf ^ 1);
            asm volatile("cp.async.wait_group 1;" ::: "memory");
        } else {
            asm volatile("cp.async.wait_group 0;" ::: "memory");
        }
        __syncthreads();

        if (kt == 0) {
#pragma unroll
            for (int dc = 0; dc < 8; dc++) {
                uint32_t off = sb + SM_Q + (uint32_t)((wq0 + lr) * QSTR + dc * 16 + lc) * 2;
                ldsm_x4(off, qf[dc][0], qf[dc][1], qf[dc][2], qf[dc][3]);
            }
        }

        const uint32_t kb_ = sb + SM_K + buf * 17408;
        const uint32_t vb_ = sb + SM_VT + buf * 18432;

        float s[4][2][4];
#pragma unroll
        for (int g = 0; g < 4; g++)
#pragma unroll
            for (int p = 0; p < 2; p++)
#pragma unroll
                for (int c = 0; c < 4; c++) s[g][p][c] = 0.f;
#pragma unroll
        for (int dc = 0; dc < 8; dc++)
#pragma unroll
            for (int g = 0; g < 4; g++) {
                uint32_t kbt[4];
                ldsm_x4(kb_ + (uint32_t)((g * 16 + lr) * QSTR + dc * 16 + lc) * 2,
                        kbt[0], kbt[1], kbt[2], kbt[3]);
                mma_f16(s[g][0], qf[dc], kbt[0], kbt[2]);
                mma_f16(s[g][1], qf[dc], kbt[1], kbt[3]);
            }

        if (kt >= 2 * qb) {
#pragma unroll
            for (int g = 0; g < 4; g++)
#pragma unroll
                for (int p = 0; p < 2; p++) {
                    int key = kt * 64 + g * 16 + p * 8 + gc;
                    if (key > q_row0)     s[g][p][0] = MASKV;
                    if (key + 1 > q_row0) s[g][p][1] = MASKV;
                    if (key > q_row0 + 8)     s[g][p][2] = MASKV;
                    if (key + 1 > q_row0 + 8) s[g][p][3] = MASKV;
                }
        }

        float t0 = MASKV, t1 = MASKV;
#pragma unroll
        for (int g = 0; g < 4; g++)
#pragma unroll
            for (int p = 0; p < 2; p++) {
                t0 = fmaxf(t0, fmaxf(s[g][p][0], s[g][p][1]));
                t1 = fmaxf(t1, fmaxf(s[g][p][2], s[g][p][3]));
            }
        t0 = fmaxf(t0, __shfl_xor_sync(0xffffffffu, t0, 1));
        t0 = fmaxf(t0, __shfl_xor_sync(0xffffffffu, t0, 2));
        t1 = fmaxf(t1, __shfl_xor_sync(0xffffffffu, t1, 1));
        t1 = fmaxf(t1, __shfl_xor_sync(0xffffffffu, t1, 2));
        float mn0 = fmaxf(m0, t0), mn1 = fmaxf(m1, t1);
        float a0 = ex2f((m0 - mn0) * CEXP), a1 = ex2f((m1 - mn1) * CEXP);
        m0 = mn0; m1 = mn1;

        uint32_t pah[4][4];
        float sum0 = 0.f, sum1 = 0.f;
#pragma unroll
        for (int g = 0; g < 4; g++)
#pragma unroll
            for (int p = 0; p < 2; p++) {
                float p0 = ex2f((s[g][p][0] - mn0) * CEXP);
                float p1 = ex2f((s[g][p][1] - mn0) * CEXP);
                float p2 = ex2f((s[g][p][2] - mn1) * CEXP);
                float p3 = ex2f((s[g][p][3] - mn1) * CEXP);
                sum0 += p0 + p1; sum1 += p2 + p3;
                pah[g][2 * p]     = pack2h(p0, p1);
                pah[g][2 * p + 1] = pack2h(p2, p3);
            }
        sum0 += __shfl_xor_sync(0xffffffffu, sum0, 1);
        sum0 += __shfl_xor_sync(0xffffffffu, sum0, 2);
        sum1 += __shfl_xor_sync(0xffffffffu, sum1, 1);
        sum1 += __shfl_xor_sync(0xffffffffu, sum1, 2);
        l0 = l0 * a0 + sum0;
        l1 = l1 * a1 + sum1;

#pragma unroll
        for (int gd = 0; gd < 8; gd++)
#pragma unroll
            for (int p = 0; p < 2; p++) {
                acc_o[gd][p][0] *= a0; acc_o[gd][p][1] *= a0;
                acc_o[gd][p][2] *= a1; acc_o[gd][p][3] *= a1;
            }

#pragma unroll
        for (int kc = 0; kc < 4; kc++)
#pragma unroll
            for (int gd = 0; gd < 8; gd++) {
                uint32_t off = (uint32_t)((gd * 16 + lr) * VTSTR + kc * 16 + lc) * 2;
                uint32_t bvh[4];
                ldsm_x4(vb_ + off, bvh[0], bvh[1], bvh[2], bvh[3]);
                mma_f16(acc_o[gd][0], pah[kc], bvh[0], bvh[2]);
                mma_f16(acc_o[gd][1], pah[kc], bvh[1], bvh[3]);
            }
        __syncthreads();
    }

    const float i0 = 1.f / l0, i1 = 1.f / l1;
    const size_t tok0 = (size_t)b * SEQ + qb * 128 + wq0 + gr;
#pragma unroll
    for (int gd = 0; gd < 8; gd++)
#pragma unroll
        for (int p = 0; p < 2; p++) {
            int col = h * HD + gd * 16 + p * 8 + gc;
            size_t o0 = tok0 * DMODEL + col, o1 = (tok0 + 8) * DMODEL + col;
            *(uint32_t*)&ath[o0] = pack2h(acc_o[gd][p][0] * i0, acc_o[gd][p][1] * i0);
            *(uint32_t*)&ath[o1] = pack2h(acc_o[gd][p][2] * i1, acc_o[gd][p][3] * i1);
        }
}

// ---------------------------------------------------------------------------
extern "C" void kernel_launch(void* const* d_in, const int* in_sizes, int n_in,
                              void* d_out, int out_size)
{
    const float* x    = (const float*)d_in[0];
    const float* Wqkv = (const float*)d_in[1];
    const float* Wo   = (const float*)d_in[2];
    float* out = (float*)d_out;

    void* p;
    cudaGetSymbolAddress(&p, g_xh);    ushort* xh  = (ushort*)p;
    cudaGetSymbolAddress(&p, g_wqkvh); ushort* wqh = (ushort*)p;
    cudaGetSymbolAddress(&p, g_woh);   ushort* woh = (ushort*)p;
    cudaGetSymbolAddress(&p, g_qkvh);  ushort* qvh = (ushort*)p;
    cudaGetSymbolAddress(&p, g_vth);   ushort* vth = (ushort*)p;
    cudaGetSymbolAddress(&p, g_ath);   ushort* ath = (ushort*)p;

    cudaFuncSetAttribute(gemm_f16<0>, cudaFuncAttributeMaxDynamicSharedMemorySize,
                         GEMM_SMEM);
    cudaFuncSetAttribute(gemm_f16<1>, cudaFuncAttributeMaxDynamicSharedMemorySize,
                         GEMM_SMEM);
    cudaFuncSetAttribute(attn_mma, cudaFuncAttributeMaxDynamicSharedMemorySize,
                         ATTN_SMEM_BYTES);

    // 0) convert inputs to fp16
    cvt_kernel<<<(NR * DMODEL / 4 + 255) / 256, 256>>>(x, xh, NR * DMODEL / 4);
    cvt_kernel<<<(TDMODEL * DMODEL / 4 + 255) / 256, 256>>>(Wqkv, wqh,
                                                            TDMODEL * DMODEL / 4);
    cvt_kernel<<<(DMODEL * DMODEL / 4 + 255) / 256, 256>>>(Wo, woh,
                                                           DMODEL * DMODEL / 4);

    // 1) fused qkv projection (fp16 1-pass, 64x64 warp tiles)
    gemm_f16<1><<<dim3(TDMODEL / 128, NR / 128), 128, GEMM_SMEM>>>(
        xh, wqh, nullptr, qvh, TDMODEL, DMODEL);

    // 2) transpose V panel
    vtrans_kernel<<<dim3(SEQ / 32, HD / 32, NB * NH), dim3(32, 8)>>>(qvh, vth);

    // 3) attention -> fp16
    attn_mma<<<dim3(16, NH, NB), 256, ATTN_SMEM_BYTES>>>(qvh, vth, ath);

    // 4) out = att @ Wo^T (fp32 out, 64x64 warp tiles)
    gemm_f16<0><<<dim3(DMODEL / 128, NR / 128), 128, GEMM_SMEM>>>(
        ath, woh, out, nullptr, DMODEL, DMODEL);
}

// round 17
// speedup vs baseline: 2.4133x; 1.0291x over previous
#include <cuda_runtime.h>
#include <cuda_bf16.h>
#include <math.h>
#include <stdint.h>

#define DMODEL 2048
#define TDMODEL 6144
#define NR 4096      // B*S rows
#define NH 16
#define HD 128
#define SEQ 2048
#define NB 2

// ---------------------------------------------------------------------------
// Scratch (no allocations allowed) — fp16 bit-planes
// ---------------------------------------------------------------------------
__device__ ushort g_xh[(size_t)NR * DMODEL];
__device__ ushort g_wqkvh[(size_t)TDMODEL * DMODEL];
__device__ ushort g_woh[(size_t)DMODEL * DMODEL];
__device__ ushort g_qkvh[(size_t)NR * TDMODEL];       // q,k,v all fp16
__device__ ushort g_ath[(size_t)NR * DMODEL];

// ---------------------------------------------------------------------------
// PTX helpers (sm_80+ portable)
// ---------------------------------------------------------------------------
__device__ __forceinline__ uint32_t smem_u32(const void* p) {
    uint32_t a;
    asm("{ .reg .u64 t; cvta.to.shared.u64 t, %1; cvt.u32.u64 %0, t; }" : "=r"(a) : "l"(p));
    return a;
}
__device__ __forceinline__ void cp16(uint32_t dst, const void* src) {
    asm volatile("cp.async.cg.shared.global [%0], [%1], 16;" :: "r"(dst), "l"(src));
}
__device__ __forceinline__ void ldsm_x4(uint32_t addr, uint32_t& r0, uint32_t& r1,
                                        uint32_t& r2, uint32_t& r3) {
    asm volatile("ldmatrix.sync.aligned.m8n8.x4.shared.b16 {%0,%1,%2,%3}, [%4];"
                 : "=r"(r0), "=r"(r1), "=r"(r2), "=r"(r3) : "r"(addr));
}
__device__ __forceinline__ void ldsm_x4_t(uint32_t addr, uint32_t& r0, uint32_t& r1,
                                          uint32_t& r2, uint32_t& r3) {
    asm volatile("ldmatrix.sync.aligned.m8n8.x4.trans.shared.b16 {%0,%1,%2,%3}, [%4];"
                 : "=r"(r0), "=r"(r1), "=r"(r2), "=r"(r3) : "r"(addr));
}
__device__ __forceinline__ void mma_f16(float* d, const uint32_t* a,
                                        uint32_t b0, uint32_t b1) {
    asm volatile(
        "mma.sync.aligned.m16n8k16.row.col.f32.f16.f16.f32 "
        "{%0,%1,%2,%3}, {%4,%5,%6,%7}, {%8,%9}, {%0,%1,%2,%3};"
        : "+f"(d[0]), "+f"(d[1]), "+f"(d[2]), "+f"(d[3])
        : "r"(a[0]), "r"(a[1]), "r"(a[2]), "r"(a[3]), "r"(b0), "r"(b1));
}
__device__ __forceinline__ float ex2f(float x) {
    float y; asm("ex2.approx.f32 %0, %1;" : "=f"(y) : "f"(x)); return y;
}
// pack {lo, hi} fp32 -> f16x2 (lo in bits [0:16))
__device__ __forceinline__ uint32_t pack2h(float lo, float hi) {
    uint32_t r;
    asm("cvt.rn.f16x2.f32 %0, %1, %2;" : "=r"(r) : "f"(hi), "f"(lo));
    return r;
}

// ---------------------------------------------------------------------------
// Convert fp32 -> fp16
// ---------------------------------------------------------------------------
__global__ void cvt_kernel(const float* __restrict__ s, ushort* __restrict__ h, int n4)
{
    int i = blockIdx.x * blockDim.x + threadIdx.x;
    if (i >= n4) return;
    float4 v = ((const float4*)s)[i];
    uint2 uh;
    uh.x = pack2h(v.x, v.y);
    uh.y = pack2h(v.z, v.w);
    ((uint2*)h)[i] = uh;
}

// ---------------------------------------------------------------------------
// mma.sync NT GEMM, single-pass fp16, fp32 accumulate.
// EMIT: 0 = fp32 -> C, 1 = fp16 -> Ch.
// CTA 128x128, 4 warps (128 threads), warp tile 64x64, BK=64 stages,
// 3-stage cp.async ring. smem rows 128 B, swizzle chunk^(row&7).
// ---------------------------------------------------------------------------
#define TS 16384u                        // 128 rows x 128 B per operand stage
#define NSTG 3
#define GEMM_SMEM (2 * NSTG * TS + 1024) // 99328

template<int EMIT>
__global__ __launch_bounds__(128, 2)
void gemm_f16(const ushort* __restrict__ A, const ushort* __restrict__ B,
              float* __restrict__ C, ushort* __restrict__ Ch, int ldc, int K)
{
    extern __shared__ char smem[];
    const uint32_t sb = (smem_u32(smem) + 1023u) & ~1023u;
    const uint32_t sA = sb;
    const uint32_t sB = sb + NSTG * TS;

    const int tid = threadIdx.x, lane = tid & 31, wid = tid >> 5;
    const int bm = blockIdx.y * 128, bn = blockIdx.x * 128;
    const int m0 = (wid & 1) * 64, n0 = (wid >> 1) * 64;

    const char* gA = (const char*)(A + (size_t)bm * K);
    const char* gB = (const char*)(B + (size_t)bn * K);

    float acc[4][8][4];
#pragma unroll
    for (int i = 0; i < 4; i++)
#pragma unroll
        for (int j = 0; j < 8; j++)
#pragma unroll
            for (int c = 0; c < 4; c++) acc[i][j][c] = 0.f;

    uint32_t cpRel[8], goRow[8];
#pragma unroll
    for (int t = 0; t < 8; t++) {
        int c = tid + t * 128;
        int row = c >> 3, ch = c & 7;
        cpRel[t] = (uint32_t)(row * 128 + (ch ^ (row & 7)) * 16);
        goRow[t] = (uint32_t)(row * K * 2 + ch * 16);
    }

    const int lr = lane & 15;
    const uint32_t hc = (uint32_t)(lane >> 4);
    uint32_t aAddr[4][2], bAddr[4][2];
#pragma unroll
    for (int mt = 0; mt < 4; mt++) {
        uint32_t row = (uint32_t)(m0 + mt * 16 + lr);
#pragma unroll
        for (int ks = 0; ks < 2; ks++)
            aAddr[mt][ks] = sA + row * 128 + ((((uint32_t)ks * 2 + hc) ^ (row & 7u)) << 4);
    }
#pragma unroll
    for (int g = 0; g < 4; g++) {
        uint32_t row = (uint32_t)(n0 + g * 16 + lr);
#pragma unroll
        for (int ks = 0; ks < 2; ks++)
            bAddr[g][ks] = sB + row * 128 + ((((uint32_t)ks * 2 + hc) ^ (row & 7u)) << 4);
    }

    auto load_stage = [&](int kb, uint32_t bufo) {
        const uint32_t gofs = (uint32_t)kb * 128;
#pragma unroll
        for (int t = 0; t < 8; t++) {
            uint32_t so = cpRel[t] + bufo;
            uint32_t go = goRow[t] + gofs;
            cp16(sA + so, gA + go);
            cp16(sB + so, gB + go);
        }
        asm volatile("cp.async.commit_group;" ::: "memory");
    };

    const int nk = K / 64;
    load_stage(0, 0);
    load_stage(1, TS);

    for (int kb0 = 0; kb0 < nk; kb0 += NSTG) {
#pragma unroll
        for (int u = 0; u < NSTG; u++) {
            const int kb = kb0 + u;
            if (kb >= nk) break;
            asm volatile("cp.async.wait_group %0;" :: "n"(NSTG - 2) : "memory");
            __syncthreads();
            {
                int nkb = kb + NSTG - 1;
                const uint32_t nbufo = (uint32_t)((u + NSTG - 1) % NSTG) * TS;
                if (nkb < nk) load_stage(nkb, nbufo);
                else asm volatile("cp.async.commit_group;" ::: "memory");
            }
            const uint32_t bufo = (uint32_t)u * TS;

#pragma unroll
            for (int ks = 0; ks < 4; ks++) {
                const int ksl = ks & 1;
                const uint32_t x = (ks & 2) ? 64u : 0u;
                uint32_t ah[4][4], bh[4][4];
#pragma unroll
                for (int mt = 0; mt < 4; mt++)
                    ldsm_x4((aAddr[mt][ksl] ^ x) + bufo,
                            ah[mt][0], ah[mt][1], ah[mt][2], ah[mt][3]);
#pragma unroll
                for (int g = 0; g < 4; g++)
                    ldsm_x4((bAddr[g][ksl] ^ x) + bufo,
                            bh[g][0], bh[g][1], bh[g][2], bh[g][3]);
#pragma unroll
                for (int mt = 0; mt < 4; mt++)
#pragma unroll
                    for (int nt = 0; nt < 8; nt++) {
                        const int g = nt >> 1, p = nt & 1;
                        mma_f16(acc[mt][nt], ah[mt], bh[g][p], bh[g][p + 2]);
                    }
            }
        }
    }

    const int gr = lane >> 2, gc = (lane & 3) * 2;
#pragma unroll
    for (int mt = 0; mt < 4; mt++)
#pragma unroll
        for (int nt = 0; nt < 8; nt++) {
            int r = bm + m0 + mt * 16 + gr;
            int cix = bn + n0 + nt * 8 + gc;
            if (EMIT == 0) {
                *(float2*)&C[(size_t)r * ldc + cix] =
                    make_float2(acc[mt][nt][0], acc[mt][nt][1]);
                *(float2*)&C[(size_t)(r + 8) * ldc + cix] =
                    make_float2(acc[mt][nt][2], acc[mt][nt][3]);
            } else {
                *(uint32_t*)&Ch[(size_t)r * ldc + cix] =
                    pack2h(acc[mt][nt][0], acc[mt][nt][1]);
                *(uint32_t*)&Ch[(size_t)(r + 8) * ldc + cix] =
                    pack2h(acc[mt][nt][2], acc[mt][nt][3]);
            }
        }
}

// ---------------------------------------------------------------------------
// Tensor-core causal flash attention, all-fp16, fp32 accum/softmax.
// V loaded straight from qkv ([tok][d] layout) and transposed by ldsm.trans.
// V smem rows: 64 tok x 256 B, swizzle chunk^(row&7).
// ---------------------------------------------------------------------------
#define QSTR 136
#define SM_Q 0
#define SM_K 34816
#define SM_VT 69632
#define ATTN_SMEM_BYTES 102400           // Q 34816 + 2x17408 K + 2x16384 V
#define CEXP 0.12751744f                 // log2(e)/sqrt(128)
#define MASKV (-1e30f)

__global__ __launch_bounds__(256, 1)
void attn_mma(const ushort* __restrict__ qkvh, ushort* __restrict__ ath)
{
    extern __shared__ char smem[];
    const uint32_t sb = smem_u32(smem);

    const int tid = threadIdx.x, lane = tid & 31, wid = tid >> 5;
    const int qb = 15 - blockIdx.x;
    const int h = blockIdx.y, b = blockIdx.z;
    const int wq0 = wid * 16;
    const int lr = lane & 15, lc = (lane >> 4) * 8;
    const int gr = lane >> 2, gc = (lane & 3) * 2;

    const char* gQ = (const char*)qkvh + ((size_t)(b * SEQ + qb * 128)) * (TDMODEL * 2)
                     + h * 256;
    const char* gK = (const char*)qkvh + ((size_t)(b * SEQ)) * (TDMODEL * 2)
                     + DMODEL * 2 + h * 256;
    const char* gV = (const char*)qkvh + ((size_t)(b * SEQ)) * (TDMODEL * 2)
                     + 2 * DMODEL * 2 + h * 256;

    {
#pragma unroll
        for (int i = 0; i < 8; i++) {
            int c = tid + i * 256;
            int row = c >> 4, coff = (c & 15) * 16;
            cp16(sb + SM_Q + row * (QSTR * 2) + coff, gQ + (size_t)row * 12288 + coff);
        }
        asm volatile("cp.async.commit_group;" ::: "memory");
    }
    auto load_stage = [&](int kt, int buf) {
        const uint32_t kb_ = sb + SM_K + buf * 17408;
        const uint32_t vb_ = sb + SM_VT + buf * 16384;
#pragma unroll
        for (int i = 0; i < 4; i++) {
            int c = tid + i * 256;
            int row = c >> 4, coff = (c & 15) * 16;
            cp16(kb_ + row * (QSTR * 2) + coff,
                 gK + (size_t)(kt * 64 + row) * 12288 + coff);
        }
#pragma unroll
        for (int i = 0; i < 4; i++) {
            int c = tid + i * 256;           // 1024 chunks: 64 rows x 16
            int row = c >> 4, ch = c & 15;
            uint32_t so = (uint32_t)(row * 256 + ((ch ^ (row & 7)) * 16));
            cp16(vb_ + so, gV + (size_t)(kt * 64 + row) * 12288 + ch * 16);
        }
        asm volatile("cp.async.commit_group;" ::: "memory");
    };
    load_stage(0, 0);

    // trans-ldsm per-lane V offsets (kc-invariant swizzle)
    const uint32_t trRow = (uint32_t)((lane & 7) | ((lane >> 4) << 3));  // k 0..15
    const uint32_t hb = (uint32_t)((lane >> 3) & 1);                     // n +8
    uint32_t vOff[8];
#pragma unroll
    for (int gd = 0; gd < 8; gd++)
        vOff[gd] = trRow * 256 + (((((uint32_t)gd << 1) | hb) ^ (trRow & 7u)) << 4);

    uint32_t qf[8][4];
    float acc_o[8][2][4];
#pragma unroll
    for (int gd = 0; gd < 8; gd++)
#pragma unroll
        for (int p = 0; p < 2; p++)
#pragma unroll
            for (int c = 0; c < 4; c++) acc_o[gd][p][c] = 0.f;
    float m0 = MASKV, m1 = MASKV, l0 = 0.f, l1 = 0.f;

    const int ktmax = 2 * qb + 1;
    const int q_row0 = qb * 128 + wq0 + gr;

    for (int kt = 0; kt <= ktmax; kt++) {
        const int buf = kt & 1;
        if (kt < ktmax) {
            load_stage(kt + 1, buf ^ 1);
            asm volatile("cp.async.wait_group 1;" ::: "memory");
        } else {
            asm volatile("cp.async.wait_group 0;" ::: "memory");
        }
        __syncthreads();

        if (kt == 0) {
#pragma unroll
            for (int dc = 0; dc < 8; dc++) {
                uint32_t off = sb + SM_Q + (uint32_t)((wq0 + lr) * QSTR + dc * 16 + lc) * 2;
                ldsm_x4(off, qf[dc][0], qf[dc][1], qf[dc][2], qf[dc][3]);
            }
        }

        const uint32_t kb_ = sb + SM_K + buf * 17408;
        const uint32_t vb_ = sb + SM_VT + buf * 16384;

        float s[4][2][4];
#pragma unroll
        for (int g = 0; g < 4; g++)
#pragma unroll
            for (int p = 0; p < 2; p++)
#pragma unroll
                for (int c = 0; c < 4; c++) s[g][p][c] = 0.f;
#pragma unroll
        for (int dc = 0; dc < 8; dc++)
#pragma unroll
            for (int g = 0; g < 4; g++) {
                uint32_t kbt[4];
                ldsm_x4(kb_ + (uint32_t)((g * 16 + lr) * QSTR + dc * 16 + lc) * 2,
                        kbt[0], kbt[1], kbt[2], kbt[3]);
                mma_f16(s[g][0], qf[dc], kbt[0], kbt[2]);
                mma_f16(s[g][1], qf[dc], kbt[1], kbt[3]);
            }

        if (kt >= 2 * qb) {
#pragma unroll
            for (int g = 0; g < 4; g++)
#pragma unroll
                for (int p = 0; p < 2; p++) {
                    int key = kt * 64 + g * 16 + p * 8 + gc;
                    if (key > q_row0)     s[g][p][0] = MASKV;
                    if (key + 1 > q_row0) s[g][p][1] = MASKV;
                    if (key > q_row0 + 8)     s[g][p][2] = MASKV;
                    if (key + 1 > q_row0 + 8) s[g][p][3] = MASKV;
                }
        }

        float t0 = MASKV, t1 = MASKV;
#pragma unroll
        for (int g = 0; g < 4; g++)
#pragma unroll
            for (int p = 0; p < 2; p++) {
                t0 = fmaxf(t0, fmaxf(s[g][p][0], s[g][p][1]));
                t1 = fmaxf(t1, fmaxf(s[g][p][2], s[g][p][3]));
            }
        t0 = fmaxf(t0, __shfl_xor_sync(0xffffffffu, t0, 1));
        t0 = fmaxf(t0, __shfl_xor_sync(0xffffffffu, t0, 2));
        t1 = fmaxf(t1, __shfl_xor_sync(0xffffffffu, t1, 1));
        t1 = fmaxf(t1, __shfl_xor_sync(0xffffffffu, t1, 2));
        float mn0 = fmaxf(m0, t0), mn1 = fmaxf(m1, t1);
        float a0 = ex2f((m0 - mn0) * CEXP), a1 = ex2f((m1 - mn1) * CEXP);
        m0 = mn0; m1 = mn1;

        uint32_t pah[4][4];
        float sum0 = 0.f, sum1 = 0.f;
#pragma unroll
        for (int g = 0; g < 4; g++)
#pragma unroll
            for (int p = 0; p < 2; p++) {
                float p0 = ex2f((s[g][p][0] - mn0) * CEXP);
                float p1 = ex2f((s[g][p][1] - mn0) * CEXP);
                float p2 = ex2f((s[g][p][2] - mn1) * CEXP);
                float p3 = ex2f((s[g][p][3] - mn1) * CEXP);
                sum0 += p0 + p1; sum1 += p2 + p3;
                pah[g][2 * p]     = pack2h(p0, p1);
                pah[g][2 * p + 1] = pack2h(p2, p3);
            }
        sum0 += __shfl_xor_sync(0xffffffffu, sum0, 1);
        sum0 += __shfl_xor_sync(0xffffffffu, sum0, 2);
        sum1 += __shfl_xor_sync(0xffffffffu, sum1, 1);
        sum1 += __shfl_xor_sync(0xffffffffu, sum1, 2);
        l0 = l0 * a0 + sum0;
        l1 = l1 * a1 + sum1;

#pragma unroll
        for (int gd = 0; gd < 8; gd++)
#pragma unroll
            for (int p = 0; p < 2; p++) {
                acc_o[gd][p][0] *= a0; acc_o[gd][p][1] *= a0;
                acc_o[gd][p][2] *= a1; acc_o[gd][p][3] *= a1;
            }

        // ---- O += P V  (fp16, V transposed by ldsm.trans) ----
#pragma unroll
        for (int kc = 0; kc < 4; kc++)
#pragma unroll
            for (int gd = 0; gd < 8; gd++) {
                uint32_t bvh[4];
                ldsm_x4_t(vb_ + vOff[gd] + (uint32_t)kc * 4096,
                          bvh[0], bvh[1], bvh[2], bvh[3]);
                mma_f16(acc_o[gd][0], pah[kc], bvh[0], bvh[2]);
                mma_f16(acc_o[gd][1], pah[kc], bvh[1], bvh[3]);
            }
        __syncthreads();
    }

    const float i0 = 1.f / l0, i1 = 1.f / l1;
    const size_t tok0 = (size_t)b * SEQ + qb * 128 + wq0 + gr;
#pragma unroll
    for (int gd = 0; gd < 8; gd++)
#pragma unroll
        for (int p = 0; p < 2; p++) {
            int col = h * HD + gd * 16 + p * 8 + gc;
            size_t o0 = tok0 * DMODEL + col, o1 = (tok0 + 8) * DMODEL + col;
            *(uint32_t*)&ath[o0] = pack2h(acc_o[gd][p][0] * i0, acc_o[gd][p][1] * i0);
            *(uint32_t*)&ath[o1] = pack2h(acc_o[gd][p][2] * i1, acc_o[gd][p][3] * i1);
        }
}

// ---------------------------------------------------------------------------
extern "C" void kernel_launch(void* const* d_in, const int* in_sizes, int n_in,
                              void* d_out, int out_size)
{
    const float* x    = (const float*)d_in[0];
    const float* Wqkv = (const float*)d_in[1];
    const float* Wo   = (const float*)d_in[2];
    float* out = (float*)d_out;

    void* p;
    cudaGetSymbolAddress(&p, g_xh);    ushort* xh  = (ushort*)p;
    cudaGetSymbolAddress(&p, g_wqkvh); ushort* wqh = (ushort*)p;
    cudaGetSymbolAddress(&p, g_woh);   ushort* woh = (ushort*)p;
    cudaGetSymbolAddress(&p, g_qkvh);  ushort* qvh = (ushort*)p;
    cudaGetSymbolAddress(&p, g_ath);   ushort* ath = (ushort*)p;

    cudaFuncSetAttribute(gemm_f16<0>, cudaFuncAttributeMaxDynamicSharedMemorySize,
                         GEMM_SMEM);
    cudaFuncSetAttribute(gemm_f16<1>, cudaFuncAttributeMaxDynamicSharedMemorySize,
                         GEMM_SMEM);
    cudaFuncSetAttribute(attn_mma, cudaFuncAttributeMaxDynamicSharedMemorySize,
                         ATTN_SMEM_BYTES);

    // 0) convert inputs to fp16
    cvt_kernel<<<(NR * DMODEL / 4 + 255) / 256, 256>>>(x, xh, NR * DMODEL / 4);
    cvt_kernel<<<(TDMODEL * DMODEL / 4 + 255) / 256, 256>>>(Wqkv, wqh,
                                                            TDMODEL * DMODEL / 4);
    cvt_kernel<<<(DMODEL * DMODEL / 4 + 255) / 256, 256>>>(Wo, woh,
                                                           DMODEL * DMODEL / 4);

    // 1) fused qkv projection (fp16 1-pass, 64x64 warp tiles)
    gemm_f16<1><<<dim3(TDMODEL / 128, NR / 128), 128, GEMM_SMEM>>>(
        xh, wqh, nullptr, qvh, TDMODEL, DMODEL);

    // 2) attention (V transposed in-kernel via ldsm.trans) -> fp16
    attn_mma<<<dim3(16, NH, NB), 256, ATTN_SMEM_BYTES>>>(qvh, ath);

    // 3) out = att @ Wo^T (fp32 out, 64x64 warp tiles)
    gemm_f16<0><<<dim3(DMODEL / 128, NR / 128), 128, GEMM_SMEM>>>(
        ath, woh, out, nullptr, DMODEL, DMODEL);
}